// round 11
// baseline (speedup 1.0000x reference)
#include <cuda_runtime.h>
#include <cuda_bf16.h>
#include <cstdint>

#define N_ATOMS 50000
#define IN_DIM 128
#define HID 256
#define N_ELEM 4
#define N_IMG 500
#define M_BLK 96          // atoms per MLP block (6 x 16-row frags)
#define NFRAG 6           // M_BLK / 16
#define MLP_THREADS 768   // 24 warps: 3(M) x 8(N), 6 warps/SMSP

// ---------------- device scratch (static allocs only) ----------------
__device__ float d_g[(size_t)N_ATOMS * IN_DIM];    // dE/dfp, 25.6 MB
__device__ int   d_perm[N_ATOMS];
__device__ int   d_offsets[N_ELEM];
__device__ int   d_counts[N_ELEM];
__device__ int   d_cursor[N_ELEM];

// fragment-prepacked weights, bf16 hi/lo split.
// layout (u32): [e][part][k16][n8][lane(32)][bidx(2)]
__device__ uint32_t d_B0pk [4 * 2 * 8  * 32 * 64];   // W0   [128k x 256n]  131072 u32
__device__ uint32_t d_B1pk [4 * 2 * 16 * 32 * 64];   // W1   [256k x 256n]  262144 u32
__device__ uint32_t d_BT1pk[4 * 2 * 16 * 32 * 64];   // W1^T [256k x 256n]  262144 u32
__device__ uint32_t d_BT0pk[4 * 2 * 16 * 16 * 64];   // W0^T [256k x 128n]  131072 u32

// prep section sizes in u32 (2 bf16 per u32)
#define C0_PREP 131072
#define C1_PREP 262144
#define C2_PREP 262144
#define C3_PREP 131072
#define PREP_TOTAL (C0_PREP + C1_PREP + C2_PREP + C3_PREP)   // 786432
#define PREP_BLOCKS (PREP_TOTAL / 256)                        // 3072

__device__ __forceinline__ int elem_of(int z) {
    return (z == 1) ? 0 : (z == 6) ? 1 : (z == 8) ? 2 : 3;
}

// ---------------- helpers ----------------
__device__ __forceinline__ void split2(float v0, float v1, uint32_t& hi, uint32_t& lo) {
    __nv_bfloat16 h0 = __float2bfloat16(v0), h1 = __float2bfloat16(v1);
    __nv_bfloat16 l0 = __float2bfloat16(v0 - __bfloat162float(h0));
    __nv_bfloat16 l1 = __float2bfloat16(v1 - __bfloat162float(h1));
    hi = ((uint32_t)__bfloat16_as_ushort(h1) << 16) | (uint32_t)__bfloat16_as_ushort(h0);
    lo = ((uint32_t)__bfloat16_as_ushort(l1) << 16) | (uint32_t)__bfloat16_as_ushort(l0);
}
__device__ __forceinline__ float2 unsplit2(uint32_t hi, uint32_t lo) {
    float a = __bfloat162float(__ushort_as_bfloat16((unsigned short)(hi & 0xffff)))
            + __bfloat162float(__ushort_as_bfloat16((unsigned short)(lo & 0xffff)));
    float b = __bfloat162float(__ushort_as_bfloat16((unsigned short)(hi >> 16)))
            + __bfloat162float(__ushort_as_bfloat16((unsigned short)(lo >> 16)));
    return make_float2(a, b);
}
// A-fragment-packed smem index (b32 units) for (row r in [0,M_BLK), col/k n)
__device__ __forceinline__ int apk_idx(int r, int n) {
    return ((((n >> 4) * NFRAG) + (r >> 4)) * 32 + ((r & 7) * 4 + ((n >> 1) & 3))) * 4
           + ((r >> 3) & 1) + (((n >> 3) & 1) << 1);
}

#define MMA_BF16(d, a, b) asm volatile( \
    "mma.sync.aligned.m16n8k16.row.col.f32.bf16.bf16.f32 " \
    "{%0,%1,%2,%3},{%4,%5,%6,%7},{%8,%9},{%0,%1,%2,%3};" \
    : "+f"((d)[0]), "+f"((d)[1]), "+f"((d)[2]), "+f"((d)[3]) \
    : "r"((a).x), "r"((a).y), "r"((a).z), "r"((a).w), "r"((b).x), "r"((b).y))

// ---------------- fused prologue: zero out | prep weights | count elems ----------------
__device__ __forceinline__ void prep_one(int i, const float* __restrict__ W0,
                                         const float* __restrict__ W1) {
    uint32_t* dst; int K16, N8, idx, mode;
    if      (i < C0_PREP)                         { dst = d_B0pk;  K16 = 8;  N8 = 32; idx = i;                         mode = 0; }
    else if (i < C0_PREP + C1_PREP)               { dst = d_B1pk;  K16 = 16; N8 = 32; idx = i - C0_PREP;               mode = 1; }
    else if (i < C0_PREP + C1_PREP + C2_PREP)     { dst = d_BT1pk; K16 = 16; N8 = 32; idx = i - C0_PREP - C1_PREP;     mode = 2; }
    else                                          { dst = d_BT0pk; K16 = 16; N8 = 16; idx = i - C0_PREP - C1_PREP - C2_PREP; mode = 3; }
    int bidx = idx & 1;
    int lane = (idx >> 1) & 31;
    int rest = idx >> 6;
    int n8  = rest % N8;  rest /= N8;
    int k16 = rest % K16; rest /= K16;
    int part = rest & 1;
    int e    = rest >> 1;
    int gg = lane >> 2, tIG = lane & 3;
    int n = n8 * 8 + gg;
    int k = k16 * 16 + bidx * 8 + tIG * 2;
    float w0, w1;
    if (mode == 0)      { const float* B = W0 + e * 32768; w0 = B[k * 256 + n]; w1 = B[(k + 1) * 256 + n]; }
    else if (mode == 1) { const float* B = W1 + e * 65536; w0 = B[k * 256 + n]; w1 = B[(k + 1) * 256 + n]; }
    else if (mode == 2) { const float* B = W1 + e * 65536; w0 = B[n * 256 + k]; w1 = B[n * 256 + k + 1]; }
    else                { const float* B = W0 + e * 32768; w0 = B[n * 256 + k]; w1 = B[n * 256 + k + 1]; }
    __nv_bfloat16 h0 = __float2bfloat16(w0), h1 = __float2bfloat16(w1);
    __nv_bfloat16 v0, v1;
    if (part == 0) { v0 = h0; v1 = h1; }
    else {
        v0 = __float2bfloat16(w0 - __bfloat162float(h0));
        v1 = __float2bfloat16(w1 - __bfloat162float(h1));
    }
    dst[idx] = ((uint32_t)__bfloat16_as_ushort(v1) << 16) | (uint32_t)__bfloat16_as_ushort(v0);
}

__global__ void pre_kernel(float* __restrict__ out, int out_n, int zb,
                           const int* __restrict__ z,
                           const float* __restrict__ W0, const float* __restrict__ W1) {
    int bid = blockIdx.x, tid = threadIdx.x;
    if (bid < zb) {
        int i = bid * 256 + tid;
        if (i < out_n) out[i] = 0.0f;
    } else if (bid < zb + PREP_BLOCKS) {
        prep_one((bid - zb) * 256 + tid, W0, W1);
    } else {
        __shared__ int c[N_ELEM];
        if (tid < N_ELEM) c[tid] = 0;
        __syncthreads();
        for (int i = tid; i < N_ATOMS; i += 256)
            atomicAdd(&c[elem_of(__ldg(&z[i]))], 1);
        __syncthreads();
        if (tid == 0) {
            int off = 0;
            for (int e = 0; e < N_ELEM; e++) {
                d_offsets[e] = off; d_counts[e] = c[e]; d_cursor[e] = off;
                off += c[e];
            }
        }
    }
}

__global__ void scatter_kernel(const int* __restrict__ z, int n) {
    int a = blockIdx.x * blockDim.x + threadIdx.x;
    bool valid = a < n;
    int myE = valid ? elem_of(z[a]) : -1;
    int lane = threadIdx.x & 31;
    #pragma unroll
    for (int e = 0; e < N_ELEM; e++) {
        unsigned m = __ballot_sync(0xffffffffu, myE == e);
        if (!m) continue;
        int leader = __ffs(m) - 1;
        int base = 0;
        if (lane == leader) base = atomicAdd(&d_cursor[e], __popc(m));
        base = __shfl_sync(0xffffffffu, base, leader);
        if (myE == e) {
            int rank = __popc(m & ((1u << lane) - 1u));
            d_perm[base + rank] = a;
        }
    }
}

// ---------------- GEMM phase (bf16x3: hi*hi + hi*lo + lo*hi) ----------------
// warp owns TWO 16-row A frags (r16base, r16base+1) and NF B n8-frags from n8base.
template <int K16, int NF, int N8TOT>
__device__ __forceinline__ void gemm_phase(
    const uint32_t* __restrict__ As, int psA,     // smem, A packed (hi at 0, lo at psA)
    const uint32_t* __restrict__ Bg, int psB,     // global, B packed
    int r16base, int n8base, int lane, float (&acc)[2][4][4])
{
    #pragma unroll 2
    for (int k16 = 0; k16 < K16; k16++) {
        uint4 ahi[2], alo[2];
        #pragma unroll
        for (int mf = 0; mf < 2; mf++) {
            int b = ((k16 * NFRAG + r16base + mf) * 32 + lane) * 4;
            ahi[mf] = *(const uint4*)&As[b];
            alo[mf] = *(const uint4*)&As[psA + b];
        }
        #pragma unroll
        for (int nf = 0; nf < NF; nf++) {
            int bb = ((k16 * N8TOT + n8base + nf) * 32 + lane) * 2;
            uint2 bhi = *(const uint2*)&Bg[bb];
            uint2 blo = *(const uint2*)&Bg[psB + bb];
            MMA_BF16(acc[0][nf], ahi[0], bhi);
            MMA_BF16(acc[1][nf], ahi[1], bhi);
            MMA_BF16(acc[0][nf], ahi[0], blo);
            MMA_BF16(acc[1][nf], ahi[1], blo);
            MMA_BF16(acc[0][nf], alo[0], bhi);
            MMA_BF16(acc[1][nf], alo[1], bhi);
        }
    }
}

// ---------------- fused MLP fwd + bwd, tensor-core ----------------
// block: 96 atoms, 768 threads = 24 warps in 3(M) x 8(N) grid; warp tile 32x32 (32x16 for B0).
__global__ void __launch_bounds__(MLP_THREADS)
mlp_mma_kernel(const float* __restrict__ fp, const int* __restrict__ image_idx,
               const float* __restrict__ b0g, const float* __restrict__ b1g,
               const float* __restrict__ W2g, const float* __restrict__ b2g,
               float* __restrict__ out_energy)
{
    const int e = blockIdx.y;
    const int cnt = d_counts[e];
    const int start = blockIdx.x * M_BLK;
    if (start >= cnt) return;
    const int off = d_offsets[e];
    const int na = min(M_BLK, cnt - start);

    extern __shared__ uint32_t smu[];
    uint32_t* buf0 = smu;                     // 24576 u32: h0 packed -> dh0 packed
    uint32_t* buf1 = smu + 24576;             // 24576 u32: fpA packed -> dh1 packed
    float*    o_s  = (float*)(smu + 49152);   // [96]
    int*      aidx = (int*)(o_s + M_BLK);     // [96]

    const int tid = threadIdx.x;
    const int warp = tid >> 5, lane = tid & 31;
    const int gg = lane >> 2, tIG = lane & 3;
    const int warpM = warp >> 3, warpN = warp & 7;   // 3 x 8
    const int r16base = warpM * 2;

    if (tid < M_BLK) {
        aidx[tid] = d_perm[off + start + min(tid, na - 1)];
        o_s[tid] = 0.0f;
    }
    __syncthreads();

    // ---- stage fingerprint tile as packed bf16 hi/lo A fragments (K=128, psA=6144) ----
    for (int p = tid; p < M_BLK * 64; p += MLP_THREADS) {
        int r = p >> 6, kp = p & 63;
        float2 v = *(const float2*)&fp[(size_t)aidx[r] * IN_DIM + 2 * kp];
        uint32_t hi, lo; split2(v.x, v.y, hi, lo);
        int idx = apk_idx(r, 2 * kp);
        buf1[idx] = hi; buf1[6144 + idx] = lo;
    }
    __syncthreads();

    const int r0 = warpM * 32 + gg;
    float acc[2][4][4];

    // ================= L0: preact0 = fpA @ W0 + b0 =================
    #pragma unroll
    for (int nf = 0; nf < 4; nf++) {
        int n0 = warpN * 32 + nf * 8 + 2 * tIG;
        float2 bb = *(const float2*)&b0g[e * HID + n0];
        acc[0][nf][0] = bb.x; acc[0][nf][1] = bb.y; acc[0][nf][2] = bb.x; acc[0][nf][3] = bb.y;
        acc[1][nf][0] = bb.x; acc[1][nf][1] = bb.y; acc[1][nf][2] = bb.x; acc[1][nf][3] = bb.y;
    }
    gemm_phase<8, 4, 32>(buf1, 6144, d_B0pk + e * 32768, 16384, r16base, warpN * 4, lane, acc);
    // epilogue: h0 = tanh -> packed into buf0 (K=256 layout, psA=12288)
    #pragma unroll
    for (int mf = 0; mf < 2; mf++) {
        int ra = r0 + mf * 16, rb = ra + 8;
        #pragma unroll
        for (int nf = 0; nf < 4; nf++) {
            int n0 = warpN * 32 + nf * 8 + 2 * tIG;
            float t0 = tanhf(acc[mf][nf][0]), t1 = tanhf(acc[mf][nf][1]);
            float t2 = tanhf(acc[mf][nf][2]), t3 = tanhf(acc[mf][nf][3]);
            uint32_t hi, lo;
            split2(t0, t1, hi, lo);
            int i0 = apk_idx(ra, n0); buf0[i0] = hi; buf0[12288 + i0] = lo;
            split2(t2, t3, hi, lo);
            int i1 = apk_idx(rb, n0); buf0[i1] = hi; buf0[12288 + i1] = lo;
        }
    }
    __syncthreads();

    // ================= L1: preact1 = h0 @ W1 + b1 =================
    #pragma unroll
    for (int nf = 0; nf < 4; nf++) {
        int n0 = warpN * 32 + nf * 8 + 2 * tIG;
        float2 bb = *(const float2*)&b1g[e * HID + n0];
        acc[0][nf][0] = bb.x; acc[0][nf][1] = bb.y; acc[0][nf][2] = bb.x; acc[0][nf][3] = bb.y;
        acc[1][nf][0] = bb.x; acc[1][nf][1] = bb.y; acc[1][nf][2] = bb.x; acc[1][nf][3] = bb.y;
    }
    gemm_phase<16, 4, 32>(buf0, 12288, d_B1pk + e * 65536, 32768, r16base, warpN * 4, lane, acc);
    // epilogue: h1 = tanh; o += h1.W2; dh1 = W2*(1-h1^2) -> packed into buf1 (psA=12288)
    #pragma unroll
    for (int mf = 0; mf < 2; mf++) {
        int ra = r0 + mf * 16, rb = ra + 8;
        float orow0 = 0.0f, orow1 = 0.0f;
        #pragma unroll
        for (int nf = 0; nf < 4; nf++) {
            int n0 = warpN * 32 + nf * 8 + 2 * tIG;
            float2 w2v = *(const float2*)&W2g[e * HID + n0];
            float t0 = tanhf(acc[mf][nf][0]), t1 = tanhf(acc[mf][nf][1]);
            float t2 = tanhf(acc[mf][nf][2]), t3 = tanhf(acc[mf][nf][3]);
            orow0 += t0 * w2v.x + t1 * w2v.y;
            orow1 += t2 * w2v.x + t3 * w2v.y;
            float d0 = w2v.x * (1.0f - t0 * t0), d1 = w2v.y * (1.0f - t1 * t1);
            float d2 = w2v.x * (1.0f - t2 * t2), d3 = w2v.y * (1.0f - t3 * t3);
            uint32_t hi, lo;
            split2(d0, d1, hi, lo);
            int i0 = apk_idx(ra, n0); buf1[i0] = hi; buf1[12288 + i0] = lo;
            split2(d2, d3, hi, lo);
            int i1 = apk_idx(rb, n0); buf1[i1] = hi; buf1[12288 + i1] = lo;
        }
        atomicAdd(&o_s[ra], orow0);
        atomicAdd(&o_s[rb], orow1);
    }
    __syncthreads();

    // energy: atomic segment-sum over images
    if (tid < na)
        atomicAdd(&out_energy[image_idx[aidx[tid]]], o_s[tid] + b2g[e]);

    // ================= B1: t = dh1 @ W1^T; dh0 = (1-h0^2)*t =================
    #pragma unroll
    for (int mf = 0; mf < 2; mf++)
        #pragma unroll
        for (int nf = 0; nf < 4; nf++)
            #pragma unroll
            for (int q = 0; q < 4; q++) acc[mf][nf][q] = 0.0f;
    gemm_phase<16, 4, 32>(buf1, 12288, d_BT1pk + e * 65536, 32768, r16base, warpN * 4, lane, acc);
    #pragma unroll
    for (int mf = 0; mf < 2; mf++) {
        int ra = r0 + mf * 16, rb = ra + 8;
        #pragma unroll
        for (int nf = 0; nf < 4; nf++) {
            int n0 = warpN * 32 + nf * 8 + 2 * tIG;
            int i0 = apk_idx(ra, n0), i1 = apk_idx(rb, n0);
            float2 h0a = unsplit2(buf0[i0], buf0[12288 + i0]);
            float2 h0b = unsplit2(buf0[i1], buf0[12288 + i1]);
            float v0 = (1.0f - h0a.x * h0a.x) * acc[mf][nf][0];
            float v1 = (1.0f - h0a.y * h0a.y) * acc[mf][nf][1];
            float v2 = (1.0f - h0b.x * h0b.x) * acc[mf][nf][2];
            float v3 = (1.0f - h0b.y * h0b.y) * acc[mf][nf][3];
            uint32_t hi, lo;
            split2(v0, v1, hi, lo); buf0[i0] = hi; buf0[12288 + i0] = lo;
            split2(v2, v3, hi, lo); buf0[i1] = hi; buf0[12288 + i1] = lo;
        }
    }
    __syncthreads();

    // ================= B0: g = dh0 @ W0^T -> d_g =================
    #pragma unroll
    for (int mf = 0; mf < 2; mf++)
        #pragma unroll
        for (int nf = 0; nf < 4; nf++)
            #pragma unroll
            for (int q = 0; q < 4; q++) acc[mf][nf][q] = 0.0f;
    gemm_phase<16, 2, 16>(buf0, 12288, d_BT0pk + e * 32768, 16384, r16base, warpN * 2, lane, acc);
    #pragma unroll
    for (int mf = 0; mf < 2; mf++) {
        int ra = r0 + mf * 16, rb = ra + 8;
        #pragma unroll
        for (int nf = 0; nf < 2; nf++) {
            int n0 = warpN * 16 + nf * 8 + 2 * tIG;
            if (ra < na)
                *(float2*)&d_g[(size_t)aidx[ra] * IN_DIM + n0] =
                    make_float2(acc[mf][nf][0], acc[mf][nf][1]);
            if (rb < na)
                *(float2*)&d_g[(size_t)aidx[rb] * IN_DIM + n0] =
                    make_float2(acc[mf][nf][2], acc[mf][nf][3]);
        }
    }
}

// ---------------- sparse force scatter: forces = -fprimes^T @ g ----------------
__global__ void force_kernel(const int* __restrict__ rows,
                             const int* __restrict__ cols,
                             const float* __restrict__ vals,
                             int nnz, float* __restrict__ forces) {
    const int4*   r4 = (const int4*)rows;
    const int4*   c4 = (const int4*)cols;
    const float4* v4 = (const float4*)vals;
    const int nnz4 = nnz >> 2;
    int i = blockIdx.x * blockDim.x + threadIdx.x;
    int stride = gridDim.x * blockDim.x;
    for (; i < nnz4; i += stride) {
        int4 r = __ldg(&r4[i]);
        int4 c = __ldg(&c4[i]);
        float4 v = __ldg(&v4[i]);
        atomicAdd(&forces[c.x], -v.x * d_g[r.x]);
        atomicAdd(&forces[c.y], -v.y * d_g[r.y]);
        atomicAdd(&forces[c.z], -v.z * d_g[r.z]);
        atomicAdd(&forces[c.w], -v.w * d_g[r.w]);
    }
    int tail = nnz & 3;
    if (tail && blockIdx.x == 0 && threadIdx.x < tail) {
        int k = (nnz & ~3) + threadIdx.x;
        atomicAdd(&forces[cols[k]], -vals[k] * d_g[rows[k]]);
    }
}

// ---------------- launch ----------------
extern "C" void kernel_launch(void* const* d_in, const int* in_sizes, int n_in,
                              void* d_out, int out_size) {
    const float* fingerprints = (const float*)d_in[0];
    const int*   atomic_num   = (const int*)  d_in[1];
    const int*   image_idx    = (const int*)  d_in[2];
    const int*   fprime_rows  = (const int*)  d_in[3];
    const int*   fprime_cols  = (const int*)  d_in[4];
    const float* fprime_vals  = (const float*)d_in[5];
    const float* W0 = (const float*)d_in[6];
    const float* b0 = (const float*)d_in[7];
    const float* W1 = (const float*)d_in[8];
    const float* b1 = (const float*)d_in[9];
    const float* W2 = (const float*)d_in[10];
    const float* b2 = (const float*)d_in[11];
    float* out = (float*)d_out;                 // [0,500): energy, [500,150500): forces
    const int nnz = in_sizes[3];

    // fused prologue: zero out | fragment-pack weights | element histogram
    const int zb = (out_size + 255) / 256;
    pre_kernel<<<zb + PREP_BLOCKS + 1, 256>>>(out, out_size, zb, atomic_num, W0, W1);

    // element bucketing
    scatter_kernel<<<(N_ATOMS + 255) / 256, 256>>>(atomic_num, N_ATOMS);

    // fused tensor-core MLP fwd+bwd: smem = 49152 u32 + o_s + aidx = 197,376 B
    const int smem_bytes = (49152 + M_BLK + M_BLK) * 4;
    cudaFuncSetAttribute(mlp_mma_kernel, cudaFuncAttributeMaxDynamicSharedMemorySize, 204 * 1024);
    dim3 grid((N_ATOMS + M_BLK - 1) / M_BLK, N_ELEM);
    mlp_mma_kernel<<<grid, MLP_THREADS, smem_bytes>>>(
        fingerprints, image_idx, b0, b1, W2, b2, out);

    // sparse force accumulation (vectorized x4)
    force_kernel<<<2048, 256>>>(fprime_rows, fprime_cols, fprime_vals, nnz, out + N_IMG);
}

// round 12
// speedup vs baseline: 1.0072x; 1.0072x over previous
#include <cuda_runtime.h>
#include <cuda_bf16.h>
#include <cstdint>

#define N_ATOMS 50000
#define IN_DIM 128
#define HID 256
#define N_ELEM 4
#define N_IMG 500
#define M_BLK 64          // atoms per MLP block
#define MLP_THREADS 512   // 16 warps: 2(M) x 8(N)

// ---------------- device scratch (static allocs only) ----------------
__device__ float d_g[(size_t)N_ATOMS * IN_DIM];    // dE/dfp, 25.6 MB
__device__ int   d_perm[N_ATOMS];
__device__ int   d_offsets[N_ELEM];
__device__ int   d_counts[N_ELEM];
__device__ int   d_cursor[N_ELEM];

// fragment-prepacked weights, bf16 hi/lo INTERLEAVED uint4 layout:
// u32 index = (((e*K16 + k16)*N8 + n8)*32 + lane)*4 + j,  j: 0=hi.b0 1=hi.b1 2=lo.b0 3=lo.b1
__device__ uint32_t d_B0pk [4 * 8  * 32 * 128];   // W0   [128k x 256n]  131072 u32
__device__ uint32_t d_B1pk [4 * 16 * 32 * 128];   // W1   [256k x 256n]  262144 u32
__device__ uint32_t d_BT1pk[4 * 16 * 32 * 128];   // W1^T [256k x 256n]  262144 u32
__device__ uint32_t d_BT0pk[4 * 16 * 16 * 128];   // W0^T [256k x 128n]  131072 u32

#define C0_PREP 131072
#define C1_PREP 262144
#define C2_PREP 262144
#define C3_PREP 131072
#define PREP_TOTAL (C0_PREP + C1_PREP + C2_PREP + C3_PREP)   // 786432
#define PREP_BLOCKS (PREP_TOTAL / 256)                        // 3072

__device__ __forceinline__ int elem_of(int z) {
    return (z == 1) ? 0 : (z == 6) ? 1 : (z == 8) ? 2 : 3;
}

// ---------------- helpers ----------------
__device__ __forceinline__ void split2(float v0, float v1, uint32_t& hi, uint32_t& lo) {
    __nv_bfloat16 h0 = __float2bfloat16(v0), h1 = __float2bfloat16(v1);
    __nv_bfloat16 l0 = __float2bfloat16(v0 - __bfloat162float(h0));
    __nv_bfloat16 l1 = __float2bfloat16(v1 - __bfloat162float(h1));
    hi = ((uint32_t)__bfloat16_as_ushort(h1) << 16) | (uint32_t)__bfloat16_as_ushort(h0);
    lo = ((uint32_t)__bfloat16_as_ushort(l1) << 16) | (uint32_t)__bfloat16_as_ushort(l0);
}
__device__ __forceinline__ float2 unsplit2(uint32_t hi, uint32_t lo) {
    float a = __bfloat162float(__ushort_as_bfloat16((unsigned short)(hi & 0xffff)))
            + __bfloat162float(__ushort_as_bfloat16((unsigned short)(lo & 0xffff)));
    float b = __bfloat162float(__ushort_as_bfloat16((unsigned short)(hi >> 16)))
            + __bfloat162float(__ushort_as_bfloat16((unsigned short)(lo >> 16)));
    return make_float2(a, b);
}
// A-fragment-packed smem index (b32 units) for (row r in [0,64), col/k n)
__device__ __forceinline__ int apk_idx(int r, int n) {
    return ((((n >> 4) << 2) | (r >> 4)) * 32 + ((r & 7) * 4 + ((n >> 1) & 3))) * 4
           + ((r >> 3) & 1) + (((n >> 3) & 1) << 1);
}

#define MMA_BF16(d, a, b) asm volatile( \
    "mma.sync.aligned.m16n8k16.row.col.f32.bf16.bf16.f32 " \
    "{%0,%1,%2,%3},{%4,%5,%6,%7},{%8,%9},{%0,%1,%2,%3};" \
    : "+f"((d)[0]), "+f"((d)[1]), "+f"((d)[2]), "+f"((d)[3]) \
    : "r"((a).x), "r"((a).y), "r"((a).z), "r"((a).w), "r"((b).x), "r"((b).y))

// ---------------- fused prologue: zero out | prep weights | count elems ----------------
__device__ __forceinline__ void prep_one(int i, const float* __restrict__ W0,
                                         const float* __restrict__ W1) {
    uint32_t* dst; int K16, N8, idx, mode;
    if      (i < C0_PREP)                     { dst = d_B0pk;  K16 = 8;  N8 = 32; idx = i;                           mode = 0; }
    else if (i < C0_PREP + C1_PREP)           { dst = d_B1pk;  K16 = 16; N8 = 32; idx = i - C0_PREP;                 mode = 1; }
    else if (i < C0_PREP + C1_PREP + C2_PREP) { dst = d_BT1pk; K16 = 16; N8 = 32; idx = i - C0_PREP - C1_PREP;       mode = 2; }
    else                                      { dst = d_BT0pk; K16 = 16; N8 = 16; idx = i - C0_PREP - C1_PREP - C2_PREP; mode = 3; }
    int j = idx & 3;              // 0=hi.b0 1=hi.b1 2=lo.b0 3=lo.b1
    int part = j >> 1, bidx = j & 1;
    int q = idx >> 2;
    int lane = q & 31; q >>= 5;
    int n8  = q % N8;  q /= N8;
    int k16 = q % K16; q /= K16;
    int e   = q;
    int gg = lane >> 2, tIG = lane & 3;
    int n = n8 * 8 + gg;
    int k = k16 * 16 + bidx * 8 + tIG * 2;
    float w0, w1;
    if (mode == 0)      { const float* B = W0 + e * 32768; w0 = B[k * 256 + n]; w1 = B[(k + 1) * 256 + n]; }
    else if (mode == 1) { const float* B = W1 + e * 65536; w0 = B[k * 256 + n]; w1 = B[(k + 1) * 256 + n]; }
    else if (mode == 2) { const float* B = W1 + e * 65536; w0 = B[n * 256 + k]; w1 = B[n * 256 + k + 1]; }
    else                { const float* B = W0 + e * 32768; w0 = B[n * 256 + k]; w1 = B[n * 256 + k + 1]; }
    __nv_bfloat16 h0 = __float2bfloat16(w0), h1 = __float2bfloat16(w1);
    __nv_bfloat16 v0, v1;
    if (part == 0) { v0 = h0; v1 = h1; }
    else {
        v0 = __float2bfloat16(w0 - __bfloat162float(h0));
        v1 = __float2bfloat16(w1 - __bfloat162float(h1));
    }
    dst[idx] = ((uint32_t)__bfloat16_as_ushort(v1) << 16) | (uint32_t)__bfloat16_as_ushort(v0);
}

__global__ void pre_kernel(float* __restrict__ out, int out_n, int zb,
                           const int* __restrict__ z,
                           const float* __restrict__ W0, const float* __restrict__ W1) {
    int bid = blockIdx.x, tid = threadIdx.x;
    if (bid < zb) {
        int i = bid * 256 + tid;
        if (i < out_n) out[i] = 0.0f;
    } else if (bid < zb + PREP_BLOCKS) {
        prep_one((bid - zb) * 256 + tid, W0, W1);
    } else {
        __shared__ int c[N_ELEM];
        if (tid < N_ELEM) c[tid] = 0;
        __syncthreads();
        for (int i = tid; i < N_ATOMS; i += 256)
            atomicAdd(&c[elem_of(__ldg(&z[i]))], 1);
        __syncthreads();
        if (tid == 0) {
            int off = 0;
            for (int e = 0; e < N_ELEM; e++) {
                d_offsets[e] = off; d_counts[e] = c[e]; d_cursor[e] = off;
                off += c[e];
            }
        }
    }
}

__global__ void scatter_kernel(const int* __restrict__ z, int n) {
    int a = blockIdx.x * blockDim.x + threadIdx.x;
    bool valid = a < n;
    int myE = valid ? elem_of(z[a]) : -1;
    int lane = threadIdx.x & 31;
    #pragma unroll
    for (int e = 0; e < N_ELEM; e++) {
        unsigned m = __ballot_sync(0xffffffffu, myE == e);
        if (!m) continue;
        int leader = __ffs(m) - 1;
        int base = 0;
        if (lane == leader) base = atomicAdd(&d_cursor[e], __popc(m));
        base = __shfl_sync(0xffffffffu, base, leader);
        if (myE == e) {
            int rank = __popc(m & ((1u << lane) - 1u));
            d_perm[base + rank] = a;
        }
    }
}

// ---------------- GEMM phase (bf16x3: hi*hi + hi*lo + lo*hi) ----------------
// Interleaved B: one LDG.128 per (k16, nf) delivers hi+lo together.
template <int K16, int NF, int N8TOT>
__device__ __forceinline__ void gemm_phase(
    const uint32_t* __restrict__ As, int psA,     // smem, A packed (hi at 0, lo at psA)
    const uint32_t* __restrict__ Bg,              // global element base, interleaved uint4
    int r16base, int n8base, int lane, float (&acc)[2][4][4])
{
    const uint32_t* Bp = Bg + ((n8base * 32 + lane) << 2);   // fold n8base+lane
    const uint32_t* Ap = As + (lane << 2);                   // fold lane
    #pragma unroll 2
    for (int k16 = 0; k16 < K16; k16++) {
        uint4 ahi[2], alo[2];
        #pragma unroll
        for (int mf = 0; mf < 2; mf++) {
            int b = (k16 * 4 + r16base + mf) * 128;
            ahi[mf] = *(const uint4*)&Ap[b];
            alo[mf] = *(const uint4*)&Ap[psA + b];
        }
        #pragma unroll
        for (int nf = 0; nf < NF; nf++) {
            uint4 bv = *(const uint4*)&Bp[(k16 * N8TOT + nf) * 128];
            uint2 bhi = make_uint2(bv.x, bv.y);
            uint2 blo = make_uint2(bv.z, bv.w);
            MMA_BF16(acc[0][nf], ahi[0], bhi);
            MMA_BF16(acc[1][nf], ahi[1], bhi);
            MMA_BF16(acc[0][nf], ahi[0], blo);
            MMA_BF16(acc[1][nf], ahi[1], blo);
            MMA_BF16(acc[0][nf], alo[0], bhi);
            MMA_BF16(acc[1][nf], alo[1], bhi);
        }
    }
}

// ---------------- fused MLP fwd + bwd, tensor-core ----------------
// block: 64 atoms, 512 threads = 16 warps in 2(M) x 8(N) grid; warp tile 32x32 (32x16 for B0).
__global__ void __launch_bounds__(MLP_THREADS)
mlp_mma_kernel(const float* __restrict__ fp, const int* __restrict__ image_idx,
               const float* __restrict__ b0g, const float* __restrict__ b1g,
               const float* __restrict__ W2g, const float* __restrict__ b2g,
               float* __restrict__ out_energy)
{
    const int e = blockIdx.y;
    const int cnt = d_counts[e];
    const int start = blockIdx.x * M_BLK;
    if (start >= cnt) return;
    const int off = d_offsets[e];
    const int na = min(M_BLK, cnt - start);

    extern __shared__ uint32_t smu[];
    uint32_t* buf0 = smu;              // 16384 u32 = 64KB : h0 packed -> dh0 packed
    uint32_t* buf1 = smu + 16384;      // 16384 u32 = 64KB : fpA packed -> dh1 packed
    float*    o_s  = (float*)(smu + 32768);   // [64]
    int*      aidx = (int*)(o_s + M_BLK);     // [64]

    const int tid = threadIdx.x;
    const int warp = tid >> 5, lane = tid & 31;
    const int gg = lane >> 2, tIG = lane & 3;
    const int warpM = warp >> 3, warpN = warp & 7;   // 2 x 8
    const int r16base = warpM * 2;

    if (tid < M_BLK) {
        aidx[tid] = d_perm[off + start + min(tid, na - 1)];
        o_s[tid] = 0.0f;
    }
    __syncthreads();

    // ---- stage fingerprint tile as packed bf16 hi/lo A fragments (K=128, psA=4096) ----
    for (int p = tid; p < M_BLK * 64; p += MLP_THREADS) {
        int r = p >> 6, kp = p & 63;
        float2 v = *(const float2*)&fp[(size_t)aidx[r] * IN_DIM + 2 * kp];
        uint32_t hi, lo; split2(v.x, v.y, hi, lo);
        int idx = apk_idx(r, 2 * kp);
        buf1[idx] = hi; buf1[4096 + idx] = lo;
    }
    __syncthreads();

    const int r0 = warpM * 32 + gg;
    float acc[2][4][4];

    // ================= L0: preact0 = fpA @ W0 + b0 =================
    #pragma unroll
    for (int nf = 0; nf < 4; nf++) {
        int n0 = warpN * 32 + nf * 8 + 2 * tIG;
        float2 bb = *(const float2*)&b0g[e * HID + n0];
        acc[0][nf][0] = bb.x; acc[0][nf][1] = bb.y; acc[0][nf][2] = bb.x; acc[0][nf][3] = bb.y;
        acc[1][nf][0] = bb.x; acc[1][nf][1] = bb.y; acc[1][nf][2] = bb.x; acc[1][nf][3] = bb.y;
    }
    gemm_phase<8, 4, 32>(buf1, 4096, d_B0pk + e * 32768, r16base, warpN * 4, lane, acc);
    // epilogue: h0 = tanh -> packed into buf0 (K=256 layout, psA=8192)
    #pragma unroll
    for (int mf = 0; mf < 2; mf++) {
        int ra = r0 + mf * 16, rb = ra + 8;
        #pragma unroll
        for (int nf = 0; nf < 4; nf++) {
            int n0 = warpN * 32 + nf * 8 + 2 * tIG;
            float t0 = tanhf(acc[mf][nf][0]), t1 = tanhf(acc[mf][nf][1]);
            float t2 = tanhf(acc[mf][nf][2]), t3 = tanhf(acc[mf][nf][3]);
            uint32_t hi, lo;
            split2(t0, t1, hi, lo);
            int i0 = apk_idx(ra, n0); buf0[i0] = hi; buf0[8192 + i0] = lo;
            split2(t2, t3, hi, lo);
            int i1 = apk_idx(rb, n0); buf0[i1] = hi; buf0[8192 + i1] = lo;
        }
    }
    __syncthreads();

    // ================= L1: preact1 = h0 @ W1 + b1 =================
    #pragma unroll
    for (int nf = 0; nf < 4; nf++) {
        int n0 = warpN * 32 + nf * 8 + 2 * tIG;
        float2 bb = *(const float2*)&b1g[e * HID + n0];
        acc[0][nf][0] = bb.x; acc[0][nf][1] = bb.y; acc[0][nf][2] = bb.x; acc[0][nf][3] = bb.y;
        acc[1][nf][0] = bb.x; acc[1][nf][1] = bb.y; acc[1][nf][2] = bb.x; acc[1][nf][3] = bb.y;
    }
    gemm_phase<16, 4, 32>(buf0, 8192, d_B1pk + e * 65536, r16base, warpN * 4, lane, acc);
    // epilogue: h1 = tanh; o += h1.W2; dh1 = W2*(1-h1^2) -> packed into buf1 (psA=8192)
    #pragma unroll
    for (int mf = 0; mf < 2; mf++) {
        int ra = r0 + mf * 16, rb = ra + 8;
        float orow0 = 0.0f, orow1 = 0.0f;
        #pragma unroll
        for (int nf = 0; nf < 4; nf++) {
            int n0 = warpN * 32 + nf * 8 + 2 * tIG;
            float2 w2v = *(const float2*)&W2g[e * HID + n0];
            float t0 = tanhf(acc[mf][nf][0]), t1 = tanhf(acc[mf][nf][1]);
            float t2 = tanhf(acc[mf][nf][2]), t3 = tanhf(acc[mf][nf][3]);
            orow0 += t0 * w2v.x + t1 * w2v.y;
            orow1 += t2 * w2v.x + t3 * w2v.y;
            float d0 = w2v.x * (1.0f - t0 * t0), d1 = w2v.y * (1.0f - t1 * t1);
            float d2 = w2v.x * (1.0f - t2 * t2), d3 = w2v.y * (1.0f - t3 * t3);
            uint32_t hi, lo;
            split2(d0, d1, hi, lo);
            int i0 = apk_idx(ra, n0); buf1[i0] = hi; buf1[8192 + i0] = lo;
            split2(d2, d3, hi, lo);
            int i1 = apk_idx(rb, n0); buf1[i1] = hi; buf1[8192 + i1] = lo;
        }
        atomicAdd(&o_s[ra], orow0);
        atomicAdd(&o_s[rb], orow1);
    }
    __syncthreads();

    // energy: atomic segment-sum over images
    if (tid < na)
        atomicAdd(&out_energy[image_idx[aidx[tid]]], o_s[tid] + b2g[e]);

    // ================= B1: t = dh1 @ W1^T; dh0 = (1-h0^2)*t =================
    #pragma unroll
    for (int mf = 0; mf < 2; mf++)
        #pragma unroll
        for (int nf = 0; nf < 4; nf++)
            #pragma unroll
            for (int q = 0; q < 4; q++) acc[mf][nf][q] = 0.0f;
    gemm_phase<16, 4, 32>(buf1, 8192, d_BT1pk + e * 65536, r16base, warpN * 4, lane, acc);
    #pragma unroll
    for (int mf = 0; mf < 2; mf++) {
        int ra = r0 + mf * 16, rb = ra + 8;
        #pragma unroll
        for (int nf = 0; nf < 4; nf++) {
            int n0 = warpN * 32 + nf * 8 + 2 * tIG;
            int i0 = apk_idx(ra, n0), i1 = apk_idx(rb, n0);
            float2 h0a = unsplit2(buf0[i0], buf0[8192 + i0]);
            float2 h0b = unsplit2(buf0[i1], buf0[8192 + i1]);
            float v0 = (1.0f - h0a.x * h0a.x) * acc[mf][nf][0];
            float v1 = (1.0f - h0a.y * h0a.y) * acc[mf][nf][1];
            float v2 = (1.0f - h0b.x * h0b.x) * acc[mf][nf][2];
            float v3 = (1.0f - h0b.y * h0b.y) * acc[mf][nf][3];
            uint32_t hi, lo;
            split2(v0, v1, hi, lo); buf0[i0] = hi; buf0[8192 + i0] = lo;
            split2(v2, v3, hi, lo); buf0[i1] = hi; buf0[8192 + i1] = lo;
        }
    }
    __syncthreads();

    // ================= B0: g = dh0 @ W0^T -> d_g =================
    #pragma unroll
    for (int mf = 0; mf < 2; mf++)
        #pragma unroll
        for (int nf = 0; nf < 4; nf++)
            #pragma unroll
            for (int q = 0; q < 4; q++) acc[mf][nf][q] = 0.0f;
    gemm_phase<16, 2, 16>(buf0, 8192, d_BT0pk + e * 32768, r16base, warpN * 2, lane, acc);
    #pragma unroll
    for (int mf = 0; mf < 2; mf++) {
        int ra = r0 + mf * 16, rb = ra + 8;
        #pragma unroll
        for (int nf = 0; nf < 2; nf++) {
            int n0 = warpN * 16 + nf * 8 + 2 * tIG;
            if (ra < na)
                *(float2*)&d_g[(size_t)aidx[ra] * IN_DIM + n0] =
                    make_float2(acc[mf][nf][0], acc[mf][nf][1]);
            if (rb < na)
                *(float2*)&d_g[(size_t)aidx[rb] * IN_DIM + n0] =
                    make_float2(acc[mf][nf][2], acc[mf][nf][3]);
        }
    }
}

// ---------------- sparse force scatter: forces = -fprimes^T @ g ----------------
__global__ void force_kernel(const int* __restrict__ rows,
                             const int* __restrict__ cols,
                             const float* __restrict__ vals,
                             int nnz, float* __restrict__ forces) {
    const int4*   r4 = (const int4*)rows;
    const int4*   c4 = (const int4*)cols;
    const float4* v4 = (const float4*)vals;
    const int nnz4 = nnz >> 2;
    int i = blockIdx.x * blockDim.x + threadIdx.x;
    int stride = gridDim.x * blockDim.x;
    for (; i < nnz4; i += stride) {
        int4 r = __ldg(&r4[i]);
        int4 c = __ldg(&c4[i]);
        float4 v = __ldg(&v4[i]);
        atomicAdd(&forces[c.x], -v.x * d_g[r.x]);
        atomicAdd(&forces[c.y], -v.y * d_g[r.y]);
        atomicAdd(&forces[c.z], -v.z * d_g[r.z]);
        atomicAdd(&forces[c.w], -v.w * d_g[r.w]);
    }
    int tail = nnz & 3;
    if (tail && blockIdx.x == 0 && threadIdx.x < tail) {
        int k = (nnz & ~3) + threadIdx.x;
        atomicAdd(&forces[cols[k]], -vals[k] * d_g[rows[k]]);
    }
}

// ---------------- launch ----------------
extern "C" void kernel_launch(void* const* d_in, const int* in_sizes, int n_in,
                              void* d_out, int out_size) {
    const float* fingerprints = (const float*)d_in[0];
    const int*   atomic_num   = (const int*)  d_in[1];
    const int*   image_idx    = (const int*)  d_in[2];
    const int*   fprime_rows  = (const int*)  d_in[3];
    const int*   fprime_cols  = (const int*)  d_in[4];
    const float* fprime_vals  = (const float*)d_in[5];
    const float* W0 = (const float*)d_in[6];
    const float* b0 = (const float*)d_in[7];
    const float* W1 = (const float*)d_in[8];
    const float* b1 = (const float*)d_in[9];
    const float* W2 = (const float*)d_in[10];
    const float* b2 = (const float*)d_in[11];
    float* out = (float*)d_out;                 // [0,500): energy, [500,150500): forces
    const int nnz = in_sizes[3];

    // fused prologue: zero out | fragment-pack weights | element histogram
    const int zb = (out_size + 255) / 256;
    pre_kernel<<<zb + PREP_BLOCKS + 1, 256>>>(out, out_size, zb, atomic_num, W0, W1);

    // element bucketing
    scatter_kernel<<<(N_ATOMS + 255) / 256, 256>>>(atomic_num, N_ATOMS);

    // fused tensor-core MLP fwd+bwd
    const int smem_bytes = (32768 + M_BLK + M_BLK) * 4;   // 131,584 B
    cudaFuncSetAttribute(mlp_mma_kernel, cudaFuncAttributeMaxDynamicSharedMemorySize, 136 * 1024);
    dim3 grid((N_ATOMS + M_BLK - 1) / M_BLK, N_ELEM);
    mlp_mma_kernel<<<grid, MLP_THREADS, smem_bytes>>>(
        fingerprints, image_idx, b0, b1, W2, b2, out);

    // sparse force accumulation (vectorized x4)
    force_kernel<<<2048, 256>>>(fprime_rows, fprime_cols, fprime_vals, nnz, out + N_IMG);
}

// round 14
// speedup vs baseline: 1.0931x; 1.0853x over previous
#include <cuda_runtime.h>
#include <cuda_fp16.h>
#include <cstdint>

#define N_ATOMS 50000
#define IN_DIM 128
#define HID 256
#define N_ELEM 4
#define N_IMG 500
#define M_BLK 64          // atoms per MLP block
#define MLP_THREADS 512   // 16 warps: 2(M) x 8(N)

// ---------------- device scratch (static allocs only) ----------------
__device__ float d_g[(size_t)N_ATOMS * IN_DIM];    // dE/dfp, 25.6 MB
__device__ int   d_perm[N_ATOMS];
__device__ int   d_offsets[N_ELEM];
__device__ int   d_counts[N_ELEM];
__device__ int   d_cursor[N_ELEM];

// fragment-prepacked weights, SINGLE fp16 (A-split two-term scheme).
// layout (u32): [e][k16][n8][lane(32)][bidx(2)]
__device__ uint32_t d_B0pk [4 * 8  * 32 * 64];   // W0   [128k x 256n]   65536 u32
__device__ uint32_t d_B1pk [4 * 16 * 32 * 64];   // W1   [256k x 256n]  131072 u32
__device__ uint32_t d_BT1pk[4 * 16 * 32 * 64];   // W1^T [256k x 256n]  131072 u32
__device__ uint32_t d_BT0pk[4 * 16 * 16 * 64];   // W0^T [256k x 128n]   65536 u32

#define C0_PREP 65536
#define C1_PREP 131072
#define C2_PREP 131072
#define C3_PREP 65536
#define PREP_TOTAL (C0_PREP + C1_PREP + C2_PREP + C3_PREP)   // 393216
#define PREP_BLOCKS (PREP_TOTAL / 256)                        // 1536

__device__ __forceinline__ int elem_of(int z) {
    return (z == 1) ? 0 : (z == 6) ? 1 : (z == 8) ? 2 : 3;
}

// ---------------- helpers (fp16 hi/lo split of fp32 pairs) ----------------
__device__ __forceinline__ void split2(float v0, float v1, uint32_t& hi, uint32_t& lo) {
    __half h0 = __float2half_rn(v0), h1 = __float2half_rn(v1);
    __half l0 = __float2half_rn(v0 - __half2float(h0));
    __half l1 = __float2half_rn(v1 - __half2float(h1));
    hi = ((uint32_t)__half_as_ushort(h1) << 16) | (uint32_t)__half_as_ushort(h0);
    lo = ((uint32_t)__half_as_ushort(l1) << 16) | (uint32_t)__half_as_ushort(l0);
}
__device__ __forceinline__ float2 unsplit2(uint32_t hi, uint32_t lo) {
    float a = __half2float(__ushort_as_half((unsigned short)(hi & 0xffff)))
            + __half2float(__ushort_as_half((unsigned short)(lo & 0xffff)));
    float b = __half2float(__ushort_as_half((unsigned short)(hi >> 16)))
            + __half2float(__ushort_as_half((unsigned short)(lo >> 16)));
    return make_float2(a, b);
}
// A-fragment-packed smem index (b32 units) for (row r in [0,64), col/k n)
__device__ __forceinline__ int apk_idx(int r, int n) {
    return ((((n >> 4) << 2) | (r >> 4)) * 32 + ((r & 7) * 4 + ((n >> 1) & 3))) * 4
           + ((r >> 3) & 1) + (((n >> 3) & 1) << 1);
}

#define MMA_F16(d, a, b) asm volatile( \
    "mma.sync.aligned.m16n8k16.row.col.f32.f16.f16.f32 " \
    "{%0,%1,%2,%3},{%4,%5,%6,%7},{%8,%9},{%0,%1,%2,%3};" \
    : "+f"((d)[0]), "+f"((d)[1]), "+f"((d)[2]), "+f"((d)[3]) \
    : "r"((a).x), "r"((a).y), "r"((a).z), "r"((a).w), "r"((b).x), "r"((b).y))

// ---------------- fused prologue: zero out | prep weights | count elems ----------------
__device__ __forceinline__ void prep_one(int i, const float* __restrict__ W0,
                                         const float* __restrict__ W1) {
    uint32_t* dst; int K16, N8, idx, mode;
    if      (i < C0_PREP)                     { dst = d_B0pk;  K16 = 8;  N8 = 32; idx = i;                           mode = 0; }
    else if (i < C0_PREP + C1_PREP)           { dst = d_B1pk;  K16 = 16; N8 = 32; idx = i - C0_PREP;                 mode = 1; }
    else if (i < C0_PREP + C1_PREP + C2_PREP) { dst = d_BT1pk; K16 = 16; N8 = 32; idx = i - C0_PREP - C1_PREP;       mode = 2; }
    else                                      { dst = d_BT0pk; K16 = 16; N8 = 16; idx = i - C0_PREP - C1_PREP - C2_PREP; mode = 3; }
    int bidx = idx & 1;
    int lane = (idx >> 1) & 31;
    int rest = idx >> 6;
    int n8  = rest % N8;  rest /= N8;
    int k16 = rest % K16; rest /= K16;
    int e   = rest;
    int gg = lane >> 2, tIG = lane & 3;
    int n = n8 * 8 + gg;
    int k = k16 * 16 + bidx * 8 + tIG * 2;
    float w0, w1;
    if (mode == 0)      { const float* B = W0 + e * 32768; w0 = B[k * 256 + n]; w1 = B[(k + 1) * 256 + n]; }
    else if (mode == 1) { const float* B = W1 + e * 65536; w0 = B[k * 256 + n]; w1 = B[(k + 1) * 256 + n]; }
    else if (mode == 2) { const float* B = W1 + e * 65536; w0 = B[n * 256 + k]; w1 = B[n * 256 + k + 1]; }
    else                { const float* B = W0 + e * 32768; w0 = B[n * 256 + k]; w1 = B[n * 256 + k + 1]; }
    __half v0 = __float2half_rn(w0), v1 = __float2half_rn(w1);
    dst[idx] = ((uint32_t)__half_as_ushort(v1) << 16) | (uint32_t)__half_as_ushort(v0);
}

__global__ void pre_kernel(float* __restrict__ out, int out_n, int zb,
                           const int* __restrict__ z,
                           const float* __restrict__ W0, const float* __restrict__ W1) {
    int bid = blockIdx.x, tid = threadIdx.x;
    if (bid < zb) {
        int i = bid * 256 + tid;
        if (i < out_n) out[i] = 0.0f;
    } else if (bid < zb + PREP_BLOCKS) {
        prep_one((bid - zb) * 256 + tid, W0, W1);
    } else {
        __shared__ int c[N_ELEM];
        if (tid < N_ELEM) c[tid] = 0;
        __syncthreads();
        for (int i = tid; i < N_ATOMS; i += 256)
            atomicAdd(&c[elem_of(__ldg(&z[i]))], 1);
        __syncthreads();
        if (tid == 0) {
            int off = 0;
            for (int e = 0; e < N_ELEM; e++) {
                d_offsets[e] = off; d_counts[e] = c[e]; d_cursor[e] = off;
                off += c[e];
            }
        }
    }
}

__global__ void scatter_kernel(const int* __restrict__ z, int n) {
    int a = blockIdx.x * blockDim.x + threadIdx.x;
    bool valid = a < n;
    int myE = valid ? elem_of(z[a]) : -1;
    int lane = threadIdx.x & 31;
    #pragma unroll
    for (int e = 0; e < N_ELEM; e++) {
        unsigned m = __ballot_sync(0xffffffffu, myE == e);
        if (!m) continue;
        int leader = __ffs(m) - 1;
        int base = 0;
        if (lane == leader) base = atomicAdd(&d_cursor[e], __popc(m));
        base = __shfl_sync(0xffffffffu, base, leader);
        if (myE == e) {
            int rank = __popc(m & ((1u << lane) - 1u));
            d_perm[base + rank] = a;
        }
    }
}

// ---------------- GEMM phase (fp16 two-term: (ahi + alo) @ b) ----------------
// warp owns TWO 16-row A frags (r16base, r16base+1) and NF B n8-frags from n8base.
template <int K16, int NF, int N8TOT>
__device__ __forceinline__ void gemm_phase(
    const uint32_t* __restrict__ As, int psA,     // smem, A packed (hi at 0, lo at psA)
    const uint32_t* __restrict__ Bg,              // global, B packed (single fp16)
    int r16base, int n8base, int lane, float (&acc)[2][4][4])
{
    #pragma unroll 2
    for (int k16 = 0; k16 < K16; k16++) {
        uint4 ahi[2], alo[2];
        #pragma unroll
        for (int mf = 0; mf < 2; mf++) {
            int b = ((k16 * 4 + r16base + mf) * 32 + lane) * 4;
            ahi[mf] = *(const uint4*)&As[b];
            alo[mf] = *(const uint4*)&As[psA + b];
        }
        #pragma unroll
        for (int nf = 0; nf < NF; nf++) {
            int bb = ((k16 * N8TOT + n8base + nf) * 32 + lane) * 2;
            uint2 bv = *(const uint2*)&Bg[bb];
            MMA_F16(acc[0][nf], ahi[0], bv);
            MMA_F16(acc[1][nf], ahi[1], bv);
            MMA_F16(acc[0][nf], alo[0], bv);
            MMA_F16(acc[1][nf], alo[1], bv);
        }
    }
}

// ---------------- fused MLP fwd + bwd, tensor-core ----------------
// block: 64 atoms, 512 threads = 16 warps in 2(M) x 8(N) grid; warp tile 32x32 (32x16 for B0).
__global__ void __launch_bounds__(MLP_THREADS)
mlp_mma_kernel(const float* __restrict__ fp, const int* __restrict__ image_idx,
               const float* __restrict__ b0g, const float* __restrict__ b1g,
               const float* __restrict__ W2g, const float* __restrict__ b2g,
               float* __restrict__ out_energy)
{
    const int e = blockIdx.y;
    const int cnt = d_counts[e];
    const int start = blockIdx.x * M_BLK;
    if (start >= cnt) return;
    const int off = d_offsets[e];
    const int na = min(M_BLK, cnt - start);

    extern __shared__ uint32_t smu[];
    uint32_t* buf0 = smu;              // 16384 u32 : h0 packed (hi/lo) -> dh0 packed
    uint32_t* buf1 = smu + 16384;      // 16384 u32 : fpA packed -> dh1 packed
    float*    o_s  = (float*)(smu + 32768);   // [64]
    int*      aidx = (int*)(o_s + M_BLK);     // [64]

    const int tid = threadIdx.x;
    const int warp = tid >> 5, lane = tid & 31;
    const int gg = lane >> 2, tIG = lane & 3;
    const int warpM = warp >> 3, warpN = warp & 7;   // 2 x 8
    const int r16base = warpM * 2;

    if (tid < M_BLK) {
        aidx[tid] = d_perm[off + start + min(tid, na - 1)];
        o_s[tid] = 0.0f;
    }
    __syncthreads();

    // ---- stage fingerprint tile as packed fp16 hi/lo A fragments (K=128, psA=4096) ----
    for (int p = tid; p < M_BLK * 64; p += MLP_THREADS) {
        int r = p >> 6, kp = p & 63;
        float2 v = *(const float2*)&fp[(size_t)aidx[r] * IN_DIM + 2 * kp];
        uint32_t hi, lo; split2(v.x, v.y, hi, lo);
        int idx = apk_idx(r, 2 * kp);
        buf1[idx] = hi; buf1[4096 + idx] = lo;
    }
    __syncthreads();

    const int r0 = warpM * 32 + gg;
    float acc[2][4][4];

    // ================= L0: preact0 = fpA @ W0 + b0 =================
    #pragma unroll
    for (int nf = 0; nf < 4; nf++) {
        int n0 = warpN * 32 + nf * 8 + 2 * tIG;
        float2 bb = *(const float2*)&b0g[e * HID + n0];
        acc[0][nf][0] = bb.x; acc[0][nf][1] = bb.y; acc[0][nf][2] = bb.x; acc[0][nf][3] = bb.y;
        acc[1][nf][0] = bb.x; acc[1][nf][1] = bb.y; acc[1][nf][2] = bb.x; acc[1][nf][3] = bb.y;
    }
    gemm_phase<8, 4, 32>(buf1, 4096, d_B0pk + e * 16384, r16base, warpN * 4, lane, acc);
    // epilogue: h0 = tanh -> packed into buf0 (K=256 layout, psA=8192)
    #pragma unroll
    for (int mf = 0; mf < 2; mf++) {
        int ra = r0 + mf * 16, rb = ra + 8;
        #pragma unroll
        for (int nf = 0; nf < 4; nf++) {
            int n0 = warpN * 32 + nf * 8 + 2 * tIG;
            float t0 = tanhf(acc[mf][nf][0]), t1 = tanhf(acc[mf][nf][1]);
            float t2 = tanhf(acc[mf][nf][2]), t3 = tanhf(acc[mf][nf][3]);
            uint32_t hi, lo;
            split2(t0, t1, hi, lo);
            int i0 = apk_idx(ra, n0); buf0[i0] = hi; buf0[8192 + i0] = lo;
            split2(t2, t3, hi, lo);
            int i1 = apk_idx(rb, n0); buf0[i1] = hi; buf0[8192 + i1] = lo;
        }
    }
    __syncthreads();

    // ================= L1: preact1 = h0 @ W1 + b1 =================
    #pragma unroll
    for (int nf = 0; nf < 4; nf++) {
        int n0 = warpN * 32 + nf * 8 + 2 * tIG;
        float2 bb = *(const float2*)&b1g[e * HID + n0];
        acc[0][nf][0] = bb.x; acc[0][nf][1] = bb.y; acc[0][nf][2] = bb.x; acc[0][nf][3] = bb.y;
        acc[1][nf][0] = bb.x; acc[1][nf][1] = bb.y; acc[1][nf][2] = bb.x; acc[1][nf][3] = bb.y;
    }
    gemm_phase<16, 4, 32>(buf0, 8192, d_B1pk + e * 32768, r16base, warpN * 4, lane, acc);
    // epilogue: h1 = tanh; o += h1.W2; dh1 = W2*(1-h1^2) -> packed into buf1 (psA=8192)
    #pragma unroll
    for (int mf = 0; mf < 2; mf++) {
        int ra = r0 + mf * 16, rb = ra + 8;
        float orow0 = 0.0f, orow1 = 0.0f;
        #pragma unroll
        for (int nf = 0; nf < 4; nf++) {
            int n0 = warpN * 32 + nf * 8 + 2 * tIG;
            float2 w2v = *(const float2*)&W2g[e * HID + n0];
            float t0 = tanhf(acc[mf][nf][0]), t1 = tanhf(acc[mf][nf][1]);
            float t2 = tanhf(acc[mf][nf][2]), t3 = tanhf(acc[mf][nf][3]);
            orow0 += t0 * w2v.x + t1 * w2v.y;
            orow1 += t2 * w2v.x + t3 * w2v.y;
            float d0 = w2v.x * (1.0f - t0 * t0), d1 = w2v.y * (1.0f - t1 * t1);
            float d2 = w2v.x * (1.0f - t2 * t2), d3 = w2v.y * (1.0f - t3 * t3);
            uint32_t hi, lo;
            split2(d0, d1, hi, lo);
            int i0 = apk_idx(ra, n0); buf1[i0] = hi; buf1[8192 + i0] = lo;
            split2(d2, d3, hi, lo);
            int i1 = apk_idx(rb, n0); buf1[i1] = hi; buf1[8192 + i1] = lo;
        }
        atomicAdd(&o_s[ra], orow0);
        atomicAdd(&o_s[rb], orow1);
    }
    __syncthreads();

    // energy: atomic segment-sum over images
    if (tid < na)
        atomicAdd(&out_energy[image_idx[aidx[tid]]], o_s[tid] + b2g[e]);

    // ================= B1: t = dh1 @ W1^T; dh0 = (1-h0^2)*t =================
    #pragma unroll
    for (int mf = 0; mf < 2; mf++)
        #pragma unroll
        for (int nf = 0; nf < 4; nf++)
            #pragma unroll
            for (int q = 0; q < 4; q++) acc[mf][nf][q] = 0.0f;
    gemm_phase<16, 4, 32>(buf1, 8192, d_BT1pk + e * 32768, r16base, warpN * 4, lane, acc);
    #pragma unroll
    for (int mf = 0; mf < 2; mf++) {
        int ra = r0 + mf * 16, rb = ra + 8;
        #pragma unroll
        for (int nf = 0; nf < 4; nf++) {
            int n0 = warpN * 32 + nf * 8 + 2 * tIG;
            int i0 = apk_idx(ra, n0), i1 = apk_idx(rb, n0);
            float2 h0a = unsplit2(buf0[i0], buf0[8192 + i0]);
            float2 h0b = unsplit2(buf0[i1], buf0[8192 + i1]);
            float v0 = (1.0f - h0a.x * h0a.x) * acc[mf][nf][0];
            float v1 = (1.0f - h0a.y * h0a.y) * acc[mf][nf][1];
            float v2 = (1.0f - h0b.x * h0b.x) * acc[mf][nf][2];
            float v3 = (1.0f - h0b.y * h0b.y) * acc[mf][nf][3];
            uint32_t hi, lo;
            split2(v0, v1, hi, lo); buf0[i0] = hi; buf0[8192 + i0] = lo;
            split2(v2, v3, hi, lo); buf0[i1] = hi; buf0[8192 + i1] = lo;
        }
    }
    __syncthreads();

    // ================= B0: g = dh0 @ W0^T -> d_g =================
    #pragma unroll
    for (int mf = 0; mf < 2; mf++)
        #pragma unroll
        for (int nf = 0; nf < 4; nf++)
            #pragma unroll
            for (int q = 0; q < 4; q++) acc[mf][nf][q] = 0.0f;
    gemm_phase<16, 2, 16>(buf0, 8192, d_BT0pk + e * 16384, r16base, warpN * 2, lane, acc);
    #pragma unroll
    for (int mf = 0; mf < 2; mf++) {
        int ra = r0 + mf * 16, rb = ra + 8;
        #pragma unroll
        for (int nf = 0; nf < 2; nf++) {
            int n0 = warpN * 16 + nf * 8 + 2 * tIG;
            if (ra < na)
                *(float2*)&d_g[(size_t)aidx[ra] * IN_DIM + n0] =
                    make_float2(acc[mf][nf][0], acc[mf][nf][1]);
            if (rb < na)
                *(float2*)&d_g[(size_t)aidx[rb] * IN_DIM + n0] =
                    make_float2(acc[mf][nf][2], acc[mf][nf][3]);
        }
    }
}

// ---------------- sparse force scatter: forces = -fprimes^T @ g ----------------
__global__ void force_kernel(const int* __restrict__ rows,
                             const int* __restrict__ cols,
                             const float* __restrict__ vals,
                             int nnz, float* __restrict__ forces) {
    const int4*   r4 = (const int4*)rows;
    const int4*   c4 = (const int4*)cols;
    const float4* v4 = (const float4*)vals;
    const int nnz4 = nnz >> 2;
    int i = blockIdx.x * blockDim.x + threadIdx.x;
    int stride = gridDim.x * blockDim.x;
    for (; i < nnz4; i += stride) {
        int4 r = __ldg(&r4[i]);
        int4 c = __ldg(&c4[i]);
        float4 v = __ldg(&v4[i]);
        atomicAdd(&forces[c.x], -v.x * d_g[r.x]);
        atomicAdd(&forces[c.y], -v.y * d_g[r.y]);
        atomicAdd(&forces[c.z], -v.z * d_g[r.z]);
        atomicAdd(&forces[c.w], -v.w * d_g[r.w]);
    }
    int tail = nnz & 3;
    if (tail && blockIdx.x == 0 && threadIdx.x < tail) {
        int k = (nnz & ~3) + threadIdx.x;
        atomicAdd(&forces[cols[k]], -vals[k] * d_g[rows[k]]);
    }
}

// ---------------- launch ----------------
extern "C" void kernel_launch(void* const* d_in, const int* in_sizes, int n_in,
                              void* d_out, int out_size) {
    const float* fingerprints = (const float*)d_in[0];
    const int*   atomic_num   = (const int*)  d_in[1];
    const int*   image_idx    = (const int*)  d_in[2];
    const int*   fprime_rows  = (const int*)  d_in[3];
    const int*   fprime_cols  = (const int*)  d_in[4];
    const float* fprime_vals  = (const float*)d_in[5];
    const float* W0 = (const float*)d_in[6];
    const float* b0 = (const float*)d_in[7];
    const float* W1 = (const float*)d_in[8];
    const float* b1 = (const float*)d_in[9];
    const float* W2 = (const float*)d_in[10];
    const float* b2 = (const float*)d_in[11];
    float* out = (float*)d_out;                 // [0,500): energy, [500,150500): forces
    const int nnz = in_sizes[3];

    // fused prologue: zero out | fragment-pack weights (fp16) | element histogram
    const int zb = (out_size + 255) / 256;
    pre_kernel<<<zb + PREP_BLOCKS + 1, 256>>>(out, out_size, zb, atomic_num, W0, W1);

    // element bucketing
    scatter_kernel<<<(N_ATOMS + 255) / 256, 256>>>(atomic_num, N_ATOMS);

    // fused tensor-core MLP fwd+bwd
    const int smem_bytes = (32768 + M_BLK + M_BLK) * 4;   // 131,584 B
    cudaFuncSetAttribute(mlp_mma_kernel, cudaFuncAttributeMaxDynamicSharedMemorySize, 136 * 1024);
    dim3 grid((N_ATOMS + M_BLK - 1) / M_BLK, N_ELEM);
    mlp_mma_kernel<<<grid, MLP_THREADS, smem_bytes>>>(
        fingerprints, image_idx, b0, b1, W2, b2, out);

    // sparse force accumulation (vectorized x4)
    force_kernel<<<2048, 256>>>(fprime_rows, fprime_cols, fprime_vals, nnz, out + N_IMG);
}

// round 15
// speedup vs baseline: 1.2398x; 1.1342x over previous
#include <cuda_runtime.h>
#include <cuda_fp16.h>
#include <cstdint>

#define N_ATOMS 50000
#define IN_DIM 128
#define HID 256
#define N_ELEM 4
#define N_IMG 500
#define M_BLK 64          // atoms per MLP block
#define MLP_THREADS 512   // 16 warps: 2(M) x 8(N)

// ---------------- device scratch (static allocs only) ----------------
__device__ float d_g[(size_t)N_ATOMS * IN_DIM];    // dE/dfp, 25.6 MB
__device__ int   d_perm[N_ATOMS];
__device__ int   d_offsets[N_ELEM];
__device__ int   d_counts[N_ELEM];
__device__ int   d_cursor[N_ELEM];

// fragment-prepacked weights, SINGLE fp16 (A-split two-term scheme).
// layout (u32): [e][k16][n8][lane(32)][bidx(2)]
__device__ uint32_t d_B0pk [4 * 8  * 32 * 64];   // W0   [128k x 256n]   65536 u32
__device__ uint32_t d_B1pk [4 * 16 * 32 * 64];   // W1   [256k x 256n]  131072 u32
__device__ uint32_t d_BT1pk[4 * 16 * 32 * 64];   // W1^T [256k x 256n]  131072 u32
__device__ uint32_t d_BT0pk[4 * 16 * 16 * 64];   // W0^T [256k x 128n]   65536 u32

#define C0_PREP 65536
#define C1_PREP 131072
#define C2_PREP 131072
#define C3_PREP 65536
#define PREP_TOTAL (C0_PREP + C1_PREP + C2_PREP + C3_PREP)   // 393216
#define PREP_BLOCKS (PREP_TOTAL / 256)                        // 1536

__device__ __forceinline__ int elem_of(int z) {
    return (z == 1) ? 0 : (z == 6) ? 1 : (z == 8) ? 2 : 3;
}

// ---------------- helpers (fp16 hi/lo split of fp32 pairs) ----------------
__device__ __forceinline__ void split2(float v0, float v1, uint32_t& hi, uint32_t& lo) {
    __half h0 = __float2half_rn(v0), h1 = __float2half_rn(v1);
    __half l0 = __float2half_rn(v0 - __half2float(h0));
    __half l1 = __float2half_rn(v1 - __half2float(h1));
    hi = ((uint32_t)__half_as_ushort(h1) << 16) | (uint32_t)__half_as_ushort(h0);
    lo = ((uint32_t)__half_as_ushort(l1) << 16) | (uint32_t)__half_as_ushort(l0);
}
__device__ __forceinline__ float2 unsplit2(uint32_t hi, uint32_t lo) {
    float a = __half2float(__ushort_as_half((unsigned short)(hi & 0xffff)))
            + __half2float(__ushort_as_half((unsigned short)(lo & 0xffff)));
    float b = __half2float(__ushort_as_half((unsigned short)(hi >> 16)))
            + __half2float(__ushort_as_half((unsigned short)(lo >> 16)));
    return make_float2(a, b);
}
// A-fragment-packed smem index (b32 units) for (row r in [0,64), col/k n)
__device__ __forceinline__ int apk_idx(int r, int n) {
    return ((((n >> 4) << 2) | (r >> 4)) * 32 + ((r & 7) * 4 + ((n >> 1) & 3))) * 4
           + ((r >> 3) & 1) + (((n >> 3) & 1) << 1);
}

#define MMA_F16(d, a, b) asm volatile( \
    "mma.sync.aligned.m16n8k16.row.col.f32.f16.f16.f32 " \
    "{%0,%1,%2,%3},{%4,%5,%6,%7},{%8,%9},{%0,%1,%2,%3};" \
    : "+f"((d)[0]), "+f"((d)[1]), "+f"((d)[2]), "+f"((d)[3]) \
    : "r"((a).x), "r"((a).y), "r"((a).z), "r"((a).w), "r"((b).x), "r"((b).y))

// ---------------- fused prologue: zero out | prep weights | count elems ----------------
__device__ __forceinline__ void prep_one(int i, const float* __restrict__ W0,
                                         const float* __restrict__ W1) {
    uint32_t* dst; int K16, N8, idx, mode;
    if      (i < C0_PREP)                     { dst = d_B0pk;  K16 = 8;  N8 = 32; idx = i;                           mode = 0; }
    else if (i < C0_PREP + C1_PREP)           { dst = d_B1pk;  K16 = 16; N8 = 32; idx = i - C0_PREP;                 mode = 1; }
    else if (i < C0_PREP + C1_PREP + C2_PREP) { dst = d_BT1pk; K16 = 16; N8 = 32; idx = i - C0_PREP - C1_PREP;       mode = 2; }
    else                                      { dst = d_BT0pk; K16 = 16; N8 = 16; idx = i - C0_PREP - C1_PREP - C2_PREP; mode = 3; }
    int bidx = idx & 1;
    int lane = (idx >> 1) & 31;
    int rest = idx >> 6;
    int n8  = rest % N8;  rest /= N8;
    int k16 = rest % K16; rest /= K16;
    int e   = rest;
    int gg = lane >> 2, tIG = lane & 3;
    int n = n8 * 8 + gg;
    int k = k16 * 16 + bidx * 8 + tIG * 2;
    float w0, w1;
    if (mode == 0)      { const float* B = W0 + e * 32768; w0 = B[k * 256 + n]; w1 = B[(k + 1) * 256 + n]; }
    else if (mode == 1) { const float* B = W1 + e * 65536; w0 = B[k * 256 + n]; w1 = B[(k + 1) * 256 + n]; }
    else if (mode == 2) { const float* B = W1 + e * 65536; w0 = B[n * 256 + k]; w1 = B[n * 256 + k + 1]; }
    else                { const float* B = W0 + e * 32768; w0 = B[n * 256 + k]; w1 = B[n * 256 + k + 1]; }
    __half v0 = __float2half_rn(w0), v1 = __float2half_rn(w1);
    dst[idx] = ((uint32_t)__half_as_ushort(v1) << 16) | (uint32_t)__half_as_ushort(v0);
}

__global__ void pre_kernel(float* __restrict__ out, int out_n, int zb,
                           const int* __restrict__ z,
                           const float* __restrict__ W0, const float* __restrict__ W1) {
    int bid = blockIdx.x, tid = threadIdx.x;
    if (bid < zb) {
        int i = bid * 256 + tid;
        if (i < out_n) out[i] = 0.0f;
    } else if (bid < zb + PREP_BLOCKS) {
        prep_one((bid - zb) * 256 + tid, W0, W1);
    } else {
        __shared__ int c[N_ELEM];
        if (tid < N_ELEM) c[tid] = 0;
        __syncthreads();
        for (int i = tid; i < N_ATOMS; i += 256)
            atomicAdd(&c[elem_of(__ldg(&z[i]))], 1);
        __syncthreads();
        if (tid == 0) {
            int off = 0;
            for (int e = 0; e < N_ELEM; e++) {
                d_offsets[e] = off; d_counts[e] = c[e]; d_cursor[e] = off;
                off += c[e];
            }
        }
    }
}

__global__ void scatter_kernel(const int* __restrict__ z, int n) {
    int a = blockIdx.x * blockDim.x + threadIdx.x;
    bool valid = a < n;
    int myE = valid ? elem_of(z[a]) : -1;
    int lane = threadIdx.x & 31;
    #pragma unroll
    for (int e = 0; e < N_ELEM; e++) {
        unsigned m = __ballot_sync(0xffffffffu, myE == e);
        if (!m) continue;
        int leader = __ffs(m) - 1;
        int base = 0;
        if (lane == leader) base = atomicAdd(&d_cursor[e], __popc(m));
        base = __shfl_sync(0xffffffffu, base, leader);
        if (myE == e) {
            int rank = __popc(m & ((1u << lane) - 1u));
            d_perm[base + rank] = a;
        }
    }
}

// ---------------- GEMM phase (fp16 two-term, software-pipelined B) ----------------
// warp owns TWO 16-row A frags and NF B n8-frags. B frags for k16+1 are
// prefetched into registers before k16's MMAs issue (hides L2 latency, no
// barriers). MMA issue is split hi-block then lo-block so same-accumulator
// reuse distance is 2*NF instructions (covers HMMA latency). Per-accumulator
// order (hi before lo) is unchanged -> bit-identical numerics.
template <int K16, int NF, int N8TOT>
__device__ __forceinline__ void gemm_phase(
    const uint32_t* __restrict__ As, int psA,     // smem, A packed (hi at 0, lo at psA)
    const uint32_t* __restrict__ Bg,              // global, B packed (single fp16)
    int r16base, int n8base, int lane, float (&acc)[2][4][4])
{
    const uint32_t* Bp = Bg + ((n8base * 32 + lane) << 1);
    uint2 bcur[NF], bnxt[NF];
    #pragma unroll
    for (int nf = 0; nf < NF; nf++)
        bcur[nf] = *(const uint2*)&Bp[nf * 64];
    #pragma unroll 2
    for (int k16 = 0; k16 < K16; k16++) {
        uint4 ahi[2], alo[2];
        #pragma unroll
        for (int mf = 0; mf < 2; mf++) {
            int b = ((k16 * 4 + r16base + mf) * 32 + lane) * 4;
            ahi[mf] = *(const uint4*)&As[b];
            alo[mf] = *(const uint4*)&As[psA + b];
        }
        if (k16 + 1 < K16) {
            #pragma unroll
            for (int nf = 0; nf < NF; nf++)
                bnxt[nf] = *(const uint2*)&Bp[((k16 + 1) * N8TOT + nf) * 64];
        }
        #pragma unroll
        for (int nf = 0; nf < NF; nf++) {
            MMA_F16(acc[0][nf], ahi[0], bcur[nf]);
            MMA_F16(acc[1][nf], ahi[1], bcur[nf]);
        }
        #pragma unroll
        for (int nf = 0; nf < NF; nf++) {
            MMA_F16(acc[0][nf], alo[0], bcur[nf]);
            MMA_F16(acc[1][nf], alo[1], bcur[nf]);
        }
        #pragma unroll
        for (int nf = 0; nf < NF; nf++)
            bcur[nf] = bnxt[nf];
    }
}

// ---------------- fused MLP fwd + bwd, tensor-core ----------------
// block: 64 atoms, 512 threads = 16 warps in 2(M) x 8(N) grid; warp tile 32x32 (32x16 for B0).
__global__ void __launch_bounds__(MLP_THREADS)
mlp_mma_kernel(const float* __restrict__ fp, const int* __restrict__ image_idx,
               const float* __restrict__ b0g, const float* __restrict__ b1g,
               const float* __restrict__ W2g, const float* __restrict__ b2g,
               float* __restrict__ out_energy)
{
    const int e = blockIdx.y;
    const int cnt = d_counts[e];
    const int start = blockIdx.x * M_BLK;
    if (start >= cnt) return;
    const int off = d_offsets[e];
    const int na = min(M_BLK, cnt - start);

    extern __shared__ uint32_t smu[];
    uint32_t* buf0 = smu;              // 16384 u32 : h0 packed (hi/lo) -> dh0 packed
    uint32_t* buf1 = smu + 16384;      // 16384 u32 : fpA packed -> dh1 packed
    float*    o_s  = (float*)(smu + 32768);   // [64]
    int*      aidx = (int*)(o_s + M_BLK);     // [64]

    const int tid = threadIdx.x;
    const int warp = tid >> 5, lane = tid & 31;
    const int gg = lane >> 2, tIG = lane & 3;
    const int warpM = warp >> 3, warpN = warp & 7;   // 2 x 8
    const int r16base = warpM * 2;

    if (tid < M_BLK) {
        aidx[tid] = d_perm[off + start + min(tid, na - 1)];
        o_s[tid] = 0.0f;
    }
    __syncthreads();

    // ---- stage fingerprint tile as packed fp16 hi/lo A fragments (K=128, psA=4096) ----
    for (int p = tid; p < M_BLK * 64; p += MLP_THREADS) {
        int r = p >> 6, kp = p & 63;
        float2 v = *(const float2*)&fp[(size_t)aidx[r] * IN_DIM + 2 * kp];
        uint32_t hi, lo; split2(v.x, v.y, hi, lo);
        int idx = apk_idx(r, 2 * kp);
        buf1[idx] = hi; buf1[4096 + idx] = lo;
    }
    __syncthreads();

    const int r0 = warpM * 32 + gg;
    float acc[2][4][4];

    // ================= L0: preact0 = fpA @ W0 + b0 =================
    #pragma unroll
    for (int nf = 0; nf < 4; nf++) {
        int n0 = warpN * 32 + nf * 8 + 2 * tIG;
        float2 bb = *(const float2*)&b0g[e * HID + n0];
        acc[0][nf][0] = bb.x; acc[0][nf][1] = bb.y; acc[0][nf][2] = bb.x; acc[0][nf][3] = bb.y;
        acc[1][nf][0] = bb.x; acc[1][nf][1] = bb.y; acc[1][nf][2] = bb.x; acc[1][nf][3] = bb.y;
    }
    gemm_phase<8, 4, 32>(buf1, 4096, d_B0pk + e * 16384, r16base, warpN * 4, lane, acc);
    // epilogue: h0 = tanh -> packed into buf0 (K=256 layout, psA=8192)
    #pragma unroll
    for (int mf = 0; mf < 2; mf++) {
        int ra = r0 + mf * 16, rb = ra + 8;
        #pragma unroll
        for (int nf = 0; nf < 4; nf++) {
            int n0 = warpN * 32 + nf * 8 + 2 * tIG;
            float t0 = tanhf(acc[mf][nf][0]), t1 = tanhf(acc[mf][nf][1]);
            float t2 = tanhf(acc[mf][nf][2]), t3 = tanhf(acc[mf][nf][3]);
            uint32_t hi, lo;
            split2(t0, t1, hi, lo);
            int i0 = apk_idx(ra, n0); buf0[i0] = hi; buf0[8192 + i0] = lo;
            split2(t2, t3, hi, lo);
            int i1 = apk_idx(rb, n0); buf0[i1] = hi; buf0[8192 + i1] = lo;
        }
    }
    __syncthreads();

    // ================= L1: preact1 = h0 @ W1 + b1 =================
    #pragma unroll
    for (int nf = 0; nf < 4; nf++) {
        int n0 = warpN * 32 + nf * 8 + 2 * tIG;
        float2 bb = *(const float2*)&b1g[e * HID + n0];
        acc[0][nf][0] = bb.x; acc[0][nf][1] = bb.y; acc[0][nf][2] = bb.x; acc[0][nf][3] = bb.y;
        acc[1][nf][0] = bb.x; acc[1][nf][1] = bb.y; acc[1][nf][2] = bb.x; acc[1][nf][3] = bb.y;
    }
    gemm_phase<16, 4, 32>(buf0, 8192, d_B1pk + e * 32768, r16base, warpN * 4, lane, acc);
    // epilogue: h1 = tanh; o += h1.W2; dh1 = W2*(1-h1^2) -> packed into buf1 (psA=8192)
    #pragma unroll
    for (int mf = 0; mf < 2; mf++) {
        int ra = r0 + mf * 16, rb = ra + 8;
        float orow0 = 0.0f, orow1 = 0.0f;
        #pragma unroll
        for (int nf = 0; nf < 4; nf++) {
            int n0 = warpN * 32 + nf * 8 + 2 * tIG;
            float2 w2v = *(const float2*)&W2g[e * HID + n0];
            float t0 = tanhf(acc[mf][nf][0]), t1 = tanhf(acc[mf][nf][1]);
            float t2 = tanhf(acc[mf][nf][2]), t3 = tanhf(acc[mf][nf][3]);
            orow0 += t0 * w2v.x + t1 * w2v.y;
            orow1 += t2 * w2v.x + t3 * w2v.y;
            float d0 = w2v.x * (1.0f - t0 * t0), d1 = w2v.y * (1.0f - t1 * t1);
            float d2 = w2v.x * (1.0f - t2 * t2), d3 = w2v.y * (1.0f - t3 * t3);
            uint32_t hi, lo;
            split2(d0, d1, hi, lo);
            int i0 = apk_idx(ra, n0); buf1[i0] = hi; buf1[8192 + i0] = lo;
            split2(d2, d3, hi, lo);
            int i1 = apk_idx(rb, n0); buf1[i1] = hi; buf1[8192 + i1] = lo;
        }
        atomicAdd(&o_s[ra], orow0);
        atomicAdd(&o_s[rb], orow1);
    }
    __syncthreads();

    // energy: atomic segment-sum over images
    if (tid < na)
        atomicAdd(&out_energy[image_idx[aidx[tid]]], o_s[tid] + b2g[e]);

    // ================= B1: t = dh1 @ W1^T; dh0 = (1-h0^2)*t =================
    #pragma unroll
    for (int mf = 0; mf < 2; mf++)
        #pragma unroll
        for (int nf = 0; nf < 4; nf++)
            #pragma unroll
            for (int q = 0; q < 4; q++) acc[mf][nf][q] = 0.0f;
    gemm_phase<16, 4, 32>(buf1, 8192, d_BT1pk + e * 32768, r16base, warpN * 4, lane, acc);
    #pragma unroll
    for (int mf = 0; mf < 2; mf++) {
        int ra = r0 + mf * 16, rb = ra + 8;
        #pragma unroll
        for (int nf = 0; nf < 4; nf++) {
            int n0 = warpN * 32 + nf * 8 + 2 * tIG;
            int i0 = apk_idx(ra, n0), i1 = apk_idx(rb, n0);
            float2 h0a = unsplit2(buf0[i0], buf0[8192 + i0]);
            float2 h0b = unsplit2(buf0[i1], buf0[8192 + i1]);
            float v0 = (1.0f - h0a.x * h0a.x) * acc[mf][nf][0];
            float v1 = (1.0f - h0a.y * h0a.y) * acc[mf][nf][1];
            float v2 = (1.0f - h0b.x * h0b.x) * acc[mf][nf][2];
            float v3 = (1.0f - h0b.y * h0b.y) * acc[mf][nf][3];
            uint32_t hi, lo;
            split2(v0, v1, hi, lo); buf0[i0] = hi; buf0[8192 + i0] = lo;
            split2(v2, v3, hi, lo); buf0[i1] = hi; buf0[8192 + i1] = lo;
        }
    }
    __syncthreads();

    // ================= B0: g = dh0 @ W0^T -> d_g =================
    #pragma unroll
    for (int mf = 0; mf < 2; mf++)
        #pragma unroll
        for (int nf = 0; nf < 4; nf++)
            #pragma unroll
            for (int q = 0; q < 4; q++) acc[mf][nf][q] = 0.0f;
    gemm_phase<16, 2, 16>(buf0, 8192, d_BT0pk + e * 16384, r16base, warpN * 2, lane, acc);
    #pragma unroll
    for (int mf = 0; mf < 2; mf++) {
        int ra = r0 + mf * 16, rb = ra + 8;
        #pragma unroll
        for (int nf = 0; nf < 2; nf++) {
            int n0 = warpN * 16 + nf * 8 + 2 * tIG;
            if (ra < na)
                *(float2*)&d_g[(size_t)aidx[ra] * IN_DIM + n0] =
                    make_float2(acc[mf][nf][0], acc[mf][nf][1]);
            if (rb < na)
                *(float2*)&d_g[(size_t)aidx[rb] * IN_DIM + n0] =
                    make_float2(acc[mf][nf][2], acc[mf][nf][3]);
        }
    }
}

// ---------------- sparse force scatter: forces = -fprimes^T @ g ----------------
__global__ void force_kernel(const int* __restrict__ rows,
                             const int* __restrict__ cols,
                             const float* __restrict__ vals,
                             int nnz, float* __restrict__ forces) {
    const int4*   r4 = (const int4*)rows;
    const int4*   c4 = (const int4*)cols;
    const float4* v4 = (const float4*)vals;
    const int nnz4 = nnz >> 2;
    int i = blockIdx.x * blockDim.x + threadIdx.x;
    int stride = gridDim.x * blockDim.x;
    for (; i < nnz4; i += stride) {
        int4 r = __ldg(&r4[i]);
        int4 c = __ldg(&c4[i]);
        float4 v = __ldg(&v4[i]);
        atomicAdd(&forces[c.x], -v.x * d_g[r.x]);
        atomicAdd(&forces[c.y], -v.y * d_g[r.y]);
        atomicAdd(&forces[c.z], -v.z * d_g[r.z]);
        atomicAdd(&forces[c.w], -v.w * d_g[r.w]);
    }
    int tail = nnz & 3;
    if (tail && blockIdx.x == 0 && threadIdx.x < tail) {
        int k = (nnz & ~3) + threadIdx.x;
        atomicAdd(&forces[cols[k]], -vals[k] * d_g[rows[k]]);
    }
}

// ---------------- launch ----------------
extern "C" void kernel_launch(void* const* d_in, const int* in_sizes, int n_in,
                              void* d_out, int out_size) {
    const float* fingerprints = (const float*)d_in[0];
    const int*   atomic_num   = (const int*)  d_in[1];
    const int*   image_idx    = (const int*)  d_in[2];
    const int*   fprime_rows  = (const int*)  d_in[3];
    const int*   fprime_cols  = (const int*)  d_in[4];
    const float* fprime_vals  = (const float*)d_in[5];
    const float* W0 = (const float*)d_in[6];
    const float* b0 = (const float*)d_in[7];
    const float* W1 = (const float*)d_in[8];
    const float* b1 = (const float*)d_in[9];
    const float* W2 = (const float*)d_in[10];
    const float* b2 = (const float*)d_in[11];
    float* out = (float*)d_out;                 // [0,500): energy, [500,150500): forces
    const int nnz = in_sizes[3];

    // fused prologue: zero out | fragment-pack weights (fp16) | element histogram
    const int zb = (out_size + 255) / 256;
    pre_kernel<<<zb + PREP_BLOCKS + 1, 256>>>(out, out_size, zb, atomic_num, W0, W1);

    // element bucketing
    scatter_kernel<<<(N_ATOMS + 255) / 256, 256>>>(atomic_num, N_ATOMS);

    // fused tensor-core MLP fwd+bwd
    const int smem_bytes = (32768 + M_BLK + M_BLK) * 4;   // 131,584 B
    cudaFuncSetAttribute(mlp_mma_kernel, cudaFuncAttributeMaxDynamicSharedMemorySize, 136 * 1024);
    dim3 grid((N_ATOMS + M_BLK - 1) / M_BLK, N_ELEM);
    mlp_mma_kernel<<<grid, MLP_THREADS, smem_bytes>>>(
        fingerprints, image_idx, b0, b1, W2, b2, out);

    // sparse force accumulation (vectorized x4)
    force_kernel<<<2048, 256>>>(fprime_rows, fprime_cols, fprime_vals, nnz, out + N_IMG);
}

// round 16
// speedup vs baseline: 1.3782x; 1.1116x over previous
#include <cuda_runtime.h>
#include <cuda_fp16.h>
#include <cstdint>

#define N_ATOMS 50000
#define IN_DIM 128
#define HID 256
#define N_ELEM 4
#define N_IMG 500
#define M_BLK 64          // atoms per MLP block
#define MLP_THREADS 512   // 16 warps: 2(M) x 8(N)

// ---------------- device scratch (static allocs only) ----------------
__device__ float d_g[(size_t)N_ATOMS * IN_DIM];    // dE/dfp, 25.6 MB
__device__ int   d_perm[N_ATOMS];
__device__ int   d_offsets[N_ELEM];
__device__ int   d_counts[N_ELEM];
__device__ int   d_cursor[N_ELEM];

// fragment-prepacked weights, SINGLE fp16 (A-split two-term scheme).
// layout (u32): [e][k16][n8][lane(32)][bidx(2)]
__device__ uint32_t d_B0pk [4 * 8  * 32 * 64];   // W0   [128k x 256n]   65536 u32
__device__ uint32_t d_B1pk [4 * 16 * 32 * 64];   // W1   [256k x 256n]  131072 u32
__device__ uint32_t d_BT1pk[4 * 16 * 32 * 64];   // W1^T [256k x 256n]  131072 u32
__device__ uint32_t d_BT0pk[4 * 16 * 16 * 64];   // W0^T [256k x 128n]   65536 u32

#define C0_PREP 65536
#define C1_PREP 131072
#define C2_PREP 131072
#define C3_PREP 65536
#define PREP_TOTAL (C0_PREP + C1_PREP + C2_PREP + C3_PREP)   // 393216
#define PREP_BLOCKS (PREP_TOTAL / 256)                        // 1536

__device__ __forceinline__ int elem_of(int z) {
    return (z == 1) ? 0 : (z == 6) ? 1 : (z == 8) ? 2 : 3;
}

// ---------------- helpers (fp16 hi/lo split of fp32 pairs) ----------------
__device__ __forceinline__ void split2(float v0, float v1, uint32_t& hi, uint32_t& lo) {
    __half h0 = __float2half_rn(v0), h1 = __float2half_rn(v1);
    __half l0 = __float2half_rn(v0 - __half2float(h0));
    __half l1 = __float2half_rn(v1 - __half2float(h1));
    hi = ((uint32_t)__half_as_ushort(h1) << 16) | (uint32_t)__half_as_ushort(h0);
    lo = ((uint32_t)__half_as_ushort(l1) << 16) | (uint32_t)__half_as_ushort(l0);
}
__device__ __forceinline__ uint32_t pack_hi2(float v0, float v1) {
    __half h0 = __float2half_rn(v0), h1 = __float2half_rn(v1);
    return ((uint32_t)__half_as_ushort(h1) << 16) | (uint32_t)__half_as_ushort(h0);
}
__device__ __forceinline__ float2 unsplit2(uint32_t hi, uint32_t lo) {
    float a = __half2float(__ushort_as_half((unsigned short)(hi & 0xffff)))
            + __half2float(__ushort_as_half((unsigned short)(lo & 0xffff)));
    float b = __half2float(__ushort_as_half((unsigned short)(hi >> 16)))
            + __half2float(__ushort_as_half((unsigned short)(lo >> 16)));
    return make_float2(a, b);
}
// A-fragment-packed smem index (b32 units) for (row r in [0,64), col/k n)
__device__ __forceinline__ int apk_idx(int r, int n) {
    return ((((n >> 4) << 2) | (r >> 4)) * 32 + ((r & 7) * 4 + ((n >> 1) & 3))) * 4
           + ((r >> 3) & 1) + (((n >> 3) & 1) << 1);
}

#define MMA_F16(d, a, b) asm volatile( \
    "mma.sync.aligned.m16n8k16.row.col.f32.f16.f16.f32 " \
    "{%0,%1,%2,%3},{%4,%5,%6,%7},{%8,%9},{%0,%1,%2,%3};" \
    : "+f"((d)[0]), "+f"((d)[1]), "+f"((d)[2]), "+f"((d)[3]) \
    : "r"((a).x), "r"((a).y), "r"((a).z), "r"((a).w), "r"((b).x), "r"((b).y))

// ---------------- fused prologue: zero out | prep weights | count elems ----------------
__device__ __forceinline__ void prep_one(int i, const float* __restrict__ W0,
                                         const float* __restrict__ W1) {
    uint32_t* dst; int K16, N8, idx, mode;
    if      (i < C0_PREP)                     { dst = d_B0pk;  K16 = 8;  N8 = 32; idx = i;                           mode = 0; }
    else if (i < C0_PREP + C1_PREP)           { dst = d_B1pk;  K16 = 16; N8 = 32; idx = i - C0_PREP;                 mode = 1; }
    else if (i < C0_PREP + C1_PREP + C2_PREP) { dst = d_BT1pk; K16 = 16; N8 = 32; idx = i - C0_PREP - C1_PREP;       mode = 2; }
    else                                      { dst = d_BT0pk; K16 = 16; N8 = 16; idx = i - C0_PREP - C1_PREP - C2_PREP; mode = 3; }
    int bidx = idx & 1;
    int lane = (idx >> 1) & 31;
    int rest = idx >> 6;
    int n8  = rest % N8;  rest /= N8;
    int k16 = rest % K16; rest /= K16;
    int e   = rest;
    int gg = lane >> 2, tIG = lane & 3;
    int n = n8 * 8 + gg;
    int k = k16 * 16 + bidx * 8 + tIG * 2;
    float w0, w1;
    if (mode == 0)      { const float* B = W0 + e * 32768; w0 = B[k * 256 + n]; w1 = B[(k + 1) * 256 + n]; }
    else if (mode == 1) { const float* B = W1 + e * 65536; w0 = B[k * 256 + n]; w1 = B[(k + 1) * 256 + n]; }
    else if (mode == 2) { const float* B = W1 + e * 65536; w0 = B[n * 256 + k]; w1 = B[n * 256 + k + 1]; }
    else                { const float* B = W0 + e * 32768; w0 = B[n * 256 + k]; w1 = B[n * 256 + k + 1]; }
    __half v0 = __float2half_rn(w0), v1 = __float2half_rn(w1);
    dst[idx] = ((uint32_t)__half_as_ushort(v1) << 16) | (uint32_t)__half_as_ushort(v0);
}

__global__ void pre_kernel(float* __restrict__ out, int out_n, int zb,
                           const int* __restrict__ z,
                           const float* __restrict__ W0, const float* __restrict__ W1) {
    int bid = blockIdx.x, tid = threadIdx.x;
    if (bid < zb) {
        int i = bid * 256 + tid;
        if (i < out_n) out[i] = 0.0f;
    } else if (bid < zb + PREP_BLOCKS) {
        prep_one((bid - zb) * 256 + tid, W0, W1);
    } else {
        __shared__ int c[N_ELEM];
        if (tid < N_ELEM) c[tid] = 0;
        __syncthreads();
        for (int i = tid; i < N_ATOMS; i += 256)
            atomicAdd(&c[elem_of(__ldg(&z[i]))], 1);
        __syncthreads();
        if (tid == 0) {
            int off = 0;
            for (int e = 0; e < N_ELEM; e++) {
                d_offsets[e] = off; d_counts[e] = c[e]; d_cursor[e] = off;
                off += c[e];
            }
        }
    }
}

__global__ void scatter_kernel(const int* __restrict__ z, int n) {
    int a = blockIdx.x * blockDim.x + threadIdx.x;
    bool valid = a < n;
    int myE = valid ? elem_of(z[a]) : -1;
    int lane = threadIdx.x & 31;
    #pragma unroll
    for (int e = 0; e < N_ELEM; e++) {
        unsigned m = __ballot_sync(0xffffffffu, myE == e);
        if (!m) continue;
        int leader = __ffs(m) - 1;
        int base = 0;
        if (lane == leader) base = atomicAdd(&d_cursor[e], __popc(m));
        base = __shfl_sync(0xffffffffu, base, leader);
        if (myE == e) {
            int rank = __popc(m & ((1u << lane) - 1u));
            d_perm[base + rank] = a;
        }
    }
}

// ---------------- GEMM phase (fp16, software-pipelined B) ----------------
// USE_LO=true : two-term A (hi+lo) — forward precision path.
// USE_LO=false: hi-only A — backward path (half the MMAs and A-LDS).
// B frags for k16+1 prefetched into registers before k16's MMAs (no barriers).
// hi-block then lo-block issue: same-acc reuse distance 2*NF covers HMMA latency.
template <bool USE_LO, int K16, int NF, int N8TOT>
__device__ __forceinline__ void gemm_phase(
    const uint32_t* __restrict__ As, int psA,     // smem, A packed (hi at 0, lo at psA)
    const uint32_t* __restrict__ Bg,              // global, B packed (single fp16)
    int r16base, int n8base, int lane, float (&acc)[2][4][4])
{
    const uint32_t* Bp = Bg + ((n8base * 32 + lane) << 1);
    uint2 bcur[NF], bnxt[NF];
    #pragma unroll
    for (int nf = 0; nf < NF; nf++)
        bcur[nf] = *(const uint2*)&Bp[nf * 64];
    #pragma unroll 2
    for (int k16 = 0; k16 < K16; k16++) {
        uint4 ahi[2], alo[2];
        #pragma unroll
        for (int mf = 0; mf < 2; mf++) {
            int b = ((k16 * 4 + r16base + mf) * 32 + lane) * 4;
            ahi[mf] = *(const uint4*)&As[b];
            if (USE_LO) alo[mf] = *(const uint4*)&As[psA + b];
        }
        if (k16 + 1 < K16) {
            #pragma unroll
            for (int nf = 0; nf < NF; nf++)
                bnxt[nf] = *(const uint2*)&Bp[((k16 + 1) * N8TOT + nf) * 64];
        }
        #pragma unroll
        for (int nf = 0; nf < NF; nf++) {
            MMA_F16(acc[0][nf], ahi[0], bcur[nf]);
            MMA_F16(acc[1][nf], ahi[1], bcur[nf]);
        }
        if (USE_LO) {
            #pragma unroll
            for (int nf = 0; nf < NF; nf++) {
                MMA_F16(acc[0][nf], alo[0], bcur[nf]);
                MMA_F16(acc[1][nf], alo[1], bcur[nf]);
            }
        }
        #pragma unroll
        for (int nf = 0; nf < NF; nf++)
            bcur[nf] = bnxt[nf];
    }
}

// ---------------- fused MLP fwd + bwd, tensor-core ----------------
// block: 64 atoms, 512 threads = 16 warps in 2(M) x 8(N) grid; warp tile 32x32 (32x16 for B0).
__global__ void __launch_bounds__(MLP_THREADS)
mlp_mma_kernel(const float* __restrict__ fp, const int* __restrict__ image_idx,
               const float* __restrict__ b0g, const float* __restrict__ b1g,
               const float* __restrict__ W2g, const float* __restrict__ b2g,
               float* __restrict__ out_energy)
{
    const int e = blockIdx.y;
    const int cnt = d_counts[e];
    const int start = blockIdx.x * M_BLK;
    if (start >= cnt) return;
    const int off = d_offsets[e];
    const int na = min(M_BLK, cnt - start);

    extern __shared__ uint32_t smu[];
    uint32_t* buf0 = smu;              // 16384 u32 : h0 packed (hi/lo) -> dh0 packed (hi only)
    uint32_t* buf1 = smu + 16384;      // 16384 u32 : fpA packed -> dh1 packed (hi only)
    float*    o_s  = (float*)(smu + 32768);   // [64]
    int*      aidx = (int*)(o_s + M_BLK);     // [64]

    const int tid = threadIdx.x;
    const int warp = tid >> 5, lane = tid & 31;
    const int gg = lane >> 2, tIG = lane & 3;
    const int warpM = warp >> 3, warpN = warp & 7;   // 2 x 8
    const int r16base = warpM * 2;

    if (tid < M_BLK) {
        aidx[tid] = d_perm[off + start + min(tid, na - 1)];
        o_s[tid] = 0.0f;
    }
    __syncthreads();

    // ---- stage fingerprint tile as packed fp16 hi/lo A fragments (K=128, psA=4096) ----
    for (int p = tid; p < M_BLK * 64; p += MLP_THREADS) {
        int r = p >> 6, kp = p & 63;
        float2 v = *(const float2*)&fp[(size_t)aidx[r] * IN_DIM + 2 * kp];
        uint32_t hi, lo; split2(v.x, v.y, hi, lo);
        int idx = apk_idx(r, 2 * kp);
        buf1[idx] = hi; buf1[4096 + idx] = lo;
    }
    __syncthreads();

    const int r0 = warpM * 32 + gg;
    float acc[2][4][4];

    // ================= L0: preact0 = fpA @ W0 + b0 (two-term A) =================
    #pragma unroll
    for (int nf = 0; nf < 4; nf++) {
        int n0 = warpN * 32 + nf * 8 + 2 * tIG;
        float2 bb = *(const float2*)&b0g[e * HID + n0];
        acc[0][nf][0] = bb.x; acc[0][nf][1] = bb.y; acc[0][nf][2] = bb.x; acc[0][nf][3] = bb.y;
        acc[1][nf][0] = bb.x; acc[1][nf][1] = bb.y; acc[1][nf][2] = bb.x; acc[1][nf][3] = bb.y;
    }
    gemm_phase<true, 8, 4, 32>(buf1, 4096, d_B0pk + e * 16384, r16base, warpN * 4, lane, acc);
    // epilogue: h0 = tanh -> packed into buf0 (K=256 layout, psA=8192)
    #pragma unroll
    for (int mf = 0; mf < 2; mf++) {
        int ra = r0 + mf * 16, rb = ra + 8;
        #pragma unroll
        for (int nf = 0; nf < 4; nf++) {
            int n0 = warpN * 32 + nf * 8 + 2 * tIG;
            float t0 = tanhf(acc[mf][nf][0]), t1 = tanhf(acc[mf][nf][1]);
            float t2 = tanhf(acc[mf][nf][2]), t3 = tanhf(acc[mf][nf][3]);
            uint32_t hi, lo;
            split2(t0, t1, hi, lo);
            int i0 = apk_idx(ra, n0); buf0[i0] = hi; buf0[8192 + i0] = lo;
            split2(t2, t3, hi, lo);
            int i1 = apk_idx(rb, n0); buf0[i1] = hi; buf0[8192 + i1] = lo;
        }
    }
    __syncthreads();

    // ================= L1: preact1 = h0 @ W1 + b1 (two-term A) =================
    #pragma unroll
    for (int nf = 0; nf < 4; nf++) {
        int n0 = warpN * 32 + nf * 8 + 2 * tIG;
        float2 bb = *(const float2*)&b1g[e * HID + n0];
        acc[0][nf][0] = bb.x; acc[0][nf][1] = bb.y; acc[0][nf][2] = bb.x; acc[0][nf][3] = bb.y;
        acc[1][nf][0] = bb.x; acc[1][nf][1] = bb.y; acc[1][nf][2] = bb.x; acc[1][nf][3] = bb.y;
    }
    gemm_phase<true, 16, 4, 32>(buf0, 8192, d_B1pk + e * 32768, r16base, warpN * 4, lane, acc);
    // epilogue: h1 = tanh; o += h1.W2; dh1 = W2*(1-h1^2) -> buf1 hi-only
    #pragma unroll
    for (int mf = 0; mf < 2; mf++) {
        int ra = r0 + mf * 16, rb = ra + 8;
        float orow0 = 0.0f, orow1 = 0.0f;
        #pragma unroll
        for (int nf = 0; nf < 4; nf++) {
            int n0 = warpN * 32 + nf * 8 + 2 * tIG;
            float2 w2v = *(const float2*)&W2g[e * HID + n0];
            float t0 = tanhf(acc[mf][nf][0]), t1 = tanhf(acc[mf][nf][1]);
            float t2 = tanhf(acc[mf][nf][2]), t3 = tanhf(acc[mf][nf][3]);
            orow0 += t0 * w2v.x + t1 * w2v.y;
            orow1 += t2 * w2v.x + t3 * w2v.y;
            float d0 = w2v.x * (1.0f - t0 * t0), d1 = w2v.y * (1.0f - t1 * t1);
            float d2 = w2v.x * (1.0f - t2 * t2), d3 = w2v.y * (1.0f - t3 * t3);
            buf1[apk_idx(ra, n0)] = pack_hi2(d0, d1);
            buf1[apk_idx(rb, n0)] = pack_hi2(d2, d3);
        }
        atomicAdd(&o_s[ra], orow0);
        atomicAdd(&o_s[rb], orow1);
    }
    __syncthreads();

    // energy: atomic segment-sum over images
    if (tid < na)
        atomicAdd(&out_energy[image_idx[aidx[tid]]], o_s[tid] + b2g[e]);

    // ================= B1: t = dh1 @ W1^T; dh0 = (1-h0^2)*t (hi-only A) =================
    #pragma unroll
    for (int mf = 0; mf < 2; mf++)
        #pragma unroll
        for (int nf = 0; nf < 4; nf++)
            #pragma unroll
            for (int q = 0; q < 4; q++) acc[mf][nf][q] = 0.0f;
    gemm_phase<false, 16, 4, 32>(buf1, 8192, d_BT1pk + e * 32768, r16base, warpN * 4, lane, acc);
    #pragma unroll
    for (int mf = 0; mf < 2; mf++) {
        int ra = r0 + mf * 16, rb = ra + 8;
        #pragma unroll
        for (int nf = 0; nf < 4; nf++) {
            int n0 = warpN * 32 + nf * 8 + 2 * tIG;
            int i0 = apk_idx(ra, n0), i1 = apk_idx(rb, n0);
            float2 h0a = unsplit2(buf0[i0], buf0[8192 + i0]);
            float2 h0b = unsplit2(buf0[i1], buf0[8192 + i1]);
            float v0 = (1.0f - h0a.x * h0a.x) * acc[mf][nf][0];
            float v1 = (1.0f - h0a.y * h0a.y) * acc[mf][nf][1];
            float v2 = (1.0f - h0b.x * h0b.x) * acc[mf][nf][2];
            float v3 = (1.0f - h0b.y * h0b.y) * acc[mf][nf][3];
            buf0[i0] = pack_hi2(v0, v1);
            buf0[i1] = pack_hi2(v2, v3);
        }
    }
    __syncthreads();

    // ================= B0: g = dh0 @ W0^T -> d_g (hi-only A) =================
    #pragma unroll
    for (int mf = 0; mf < 2; mf++)
        #pragma unroll
        for (int nf = 0; nf < 4; nf++)
            #pragma unroll
            for (int q = 0; q < 4; q++) acc[mf][nf][q] = 0.0f;
    gemm_phase<false, 16, 2, 16>(buf0, 8192, d_BT0pk + e * 16384, r16base, warpN * 2, lane, acc);
    #pragma unroll
    for (int mf = 0; mf < 2; mf++) {
        int ra = r0 + mf * 16, rb = ra + 8;
        #pragma unroll
        for (int nf = 0; nf < 2; nf++) {
            int n0 = warpN * 16 + nf * 8 + 2 * tIG;
            if (ra < na)
                *(float2*)&d_g[(size_t)aidx[ra] * IN_DIM + n0] =
                    make_float2(acc[mf][nf][0], acc[mf][nf][1]);
            if (rb < na)
                *(float2*)&d_g[(size_t)aidx[rb] * IN_DIM + n0] =
                    make_float2(acc[mf][nf][2], acc[mf][nf][3]);
        }
    }
}

// ---------------- sparse force scatter: forces = -fprimes^T @ g ----------------
__global__ void force_kernel(const int* __restrict__ rows,
                             const int* __restrict__ cols,
                             const float* __restrict__ vals,
                             int nnz, float* __restrict__ forces) {
    const int4*   r4 = (const int4*)rows;
    const int4*   c4 = (const int4*)cols;
    const float4* v4 = (const float4*)vals;
    const int nnz4 = nnz >> 2;
    int i = blockIdx.x * blockDim.x + threadIdx.x;
    int stride = gridDim.x * blockDim.x;
    for (; i < nnz4; i += stride) {
        int4 r = __ldg(&r4[i]);
        int4 c = __ldg(&c4[i]);
        float4 v = __ldg(&v4[i]);
        atomicAdd(&forces[c.x], -v.x * d_g[r.x]);
        atomicAdd(&forces[c.y], -v.y * d_g[r.y]);
        atomicAdd(&forces[c.z], -v.z * d_g[r.z]);
        atomicAdd(&forces[c.w], -v.w * d_g[r.w]);
    }
    int tail = nnz & 3;
    if (tail && blockIdx.x == 0 && threadIdx.x < tail) {
        int k = (nnz & ~3) + threadIdx.x;
        atomicAdd(&forces[cols[k]], -vals[k] * d_g[rows[k]]);
    }
}

// ---------------- launch ----------------
extern "C" void kernel_launch(void* const* d_in, const int* in_sizes, int n_in,
                              void* d_out, int out_size) {
    const float* fingerprints = (const float*)d_in[0];
    const int*   atomic_num   = (const int*)  d_in[1];
    const int*   image_idx    = (const int*)  d_in[2];
    const int*   fprime_rows  = (const int*)  d_in[3];
    const int*   fprime_cols  = (const int*)  d_in[4];
    const float* fprime_vals  = (const float*)d_in[5];
    const float* W0 = (const float*)d_in[6];
    const float* b0 = (const float*)d_in[7];
    const float* W1 = (const float*)d_in[8];
    const float* b1 = (const float*)d_in[9];
    const float* W2 = (const float*)d_in[10];
    const float* b2 = (const float*)d_in[11];
    float* out = (float*)d_out;                 // [0,500): energy, [500,150500): forces
    const int nnz = in_sizes[3];

    // fused prologue: zero out | fragment-pack weights (fp16) | element histogram
    const int zb = (out_size + 255) / 256;
    pre_kernel<<<zb + PREP_BLOCKS + 1, 256>>>(out, out_size, zb, atomic_num, W0, W1);

    // element bucketing
    scatter_kernel<<<(N_ATOMS + 255) / 256, 256>>>(atomic_num, N_ATOMS);

    // fused tensor-core MLP fwd+bwd
    const int smem_bytes = (32768 + M_BLK + M_BLK) * 4;   // 131,584 B
    cudaFuncSetAttribute(mlp_mma_kernel, cudaFuncAttributeMaxDynamicSharedMemorySize, 136 * 1024);
    dim3 grid((N_ATOMS + M_BLK - 1) / M_BLK, N_ELEM);
    mlp_mma_kernel<<<grid, MLP_THREADS, smem_bytes>>>(
        fingerprints, image_idx, b0, b1, W2, b2, out);

    // sparse force accumulation (vectorized x4)
    force_kernel<<<2048, 256>>>(fprime_rows, fprime_cols, fprime_vals, nnz, out + N_IMG);
}

// round 17
// speedup vs baseline: 1.4027x; 1.0178x over previous
#include <cuda_runtime.h>
#include <cuda_fp16.h>
#include <cstdint>

#define N_ATOMS 50000
#define IN_DIM 128
#define HID 256
#define N_ELEM 4
#define N_IMG 500
#define M_BLK 64          // atoms per MLP block
#define MLP_THREADS 512   // 16 warps: 2(M) x 8(N)

// ---------------- device scratch (static allocs only) ----------------
__device__ float d_g[(size_t)N_ATOMS * IN_DIM];    // dE/dfp, 25.6 MB
__device__ int   d_perm[N_ATOMS];
__device__ int   d_offsets[N_ELEM];
__device__ int   d_counts[N_ELEM];
__device__ int   d_cursor[N_ELEM];

// fragment-prepacked weights, SINGLE fp16 (A-split two-term scheme).
// layout (u32): [e][k16][n8][lane(32)][bidx(2)]
__device__ uint32_t d_B0pk [4 * 8  * 32 * 64];   // W0   [128k x 256n]   65536 u32
__device__ uint32_t d_B1pk [4 * 16 * 32 * 64];   // W1   [256k x 256n]  131072 u32
__device__ uint32_t d_BT1pk[4 * 16 * 32 * 64];   // W1^T [256k x 256n]  131072 u32
__device__ uint32_t d_BT0pk[4 * 16 * 16 * 64];   // W0^T [256k x 128n]   65536 u32

#define C0_PREP 65536
#define C1_PREP 131072
#define C2_PREP 131072
#define C3_PREP 65536
#define PREP_TOTAL (C0_PREP + C1_PREP + C2_PREP + C3_PREP)   // 393216
#define PREP_BLOCKS (PREP_TOTAL / 256)                        // 1536

__device__ __forceinline__ int elem_of(int z) {
    return (z == 1) ? 0 : (z == 6) ? 1 : (z == 8) ? 2 : 3;
}

// ---------------- helpers (fp16 hi/lo split of fp32 pairs) ----------------
__device__ __forceinline__ void split2(float v0, float v1, uint32_t& hi, uint32_t& lo) {
    __half h0 = __float2half_rn(v0), h1 = __float2half_rn(v1);
    __half l0 = __float2half_rn(v0 - __half2float(h0));
    __half l1 = __float2half_rn(v1 - __half2float(h1));
    hi = ((uint32_t)__half_as_ushort(h1) << 16) | (uint32_t)__half_as_ushort(h0);
    lo = ((uint32_t)__half_as_ushort(l1) << 16) | (uint32_t)__half_as_ushort(l0);
}
__device__ __forceinline__ uint32_t pack_hi2(float v0, float v1) {
    __half h0 = __float2half_rn(v0), h1 = __float2half_rn(v1);
    return ((uint32_t)__half_as_ushort(h1) << 16) | (uint32_t)__half_as_ushort(h0);
}
__device__ __forceinline__ float2 unsplit2(uint32_t hi, uint32_t lo) {
    float a = __half2float(__ushort_as_half((unsigned short)(hi & 0xffff)))
            + __half2float(__ushort_as_half((unsigned short)(lo & 0xffff)));
    float b = __half2float(__ushort_as_half((unsigned short)(hi >> 16)))
            + __half2float(__ushort_as_half((unsigned short)(lo >> 16)));
    return make_float2(a, b);
}
// A-fragment-packed smem index (b32 units) for (row r in [0,64), col/k n)
__device__ __forceinline__ int apk_idx(int r, int n) {
    return ((((n >> 4) << 2) | (r >> 4)) * 32 + ((r & 7) * 4 + ((n >> 1) & 3))) * 4
           + ((r >> 3) & 1) + (((n >> 3) & 1) << 1);
}

#define MMA_F16(d, a, b) asm volatile( \
    "mma.sync.aligned.m16n8k16.row.col.f32.f16.f16.f32 " \
    "{%0,%1,%2,%3},{%4,%5,%6,%7},{%8,%9},{%0,%1,%2,%3};" \
    : "+f"((d)[0]), "+f"((d)[1]), "+f"((d)[2]), "+f"((d)[3]) \
    : "r"((a).x), "r"((a).y), "r"((a).z), "r"((a).w), "r"((b).x), "r"((b).y))

// ---------------- fused prologue: zero out | prep weights | count elems ----------------
__device__ __forceinline__ void prep_one(int i, const float* __restrict__ W0,
                                         const float* __restrict__ W1) {
    uint32_t* dst; int K16, N8, idx, mode;
    if      (i < C0_PREP)                     { dst = d_B0pk;  K16 = 8;  N8 = 32; idx = i;                           mode = 0; }
    else if (i < C0_PREP + C1_PREP)           { dst = d_B1pk;  K16 = 16; N8 = 32; idx = i - C0_PREP;                 mode = 1; }
    else if (i < C0_PREP + C1_PREP + C2_PREP) { dst = d_BT1pk; K16 = 16; N8 = 32; idx = i - C0_PREP - C1_PREP;       mode = 2; }
    else                                      { dst = d_BT0pk; K16 = 16; N8 = 16; idx = i - C0_PREP - C1_PREP - C2_PREP; mode = 3; }
    int bidx = idx & 1;
    int lane = (idx >> 1) & 31;
    int rest = idx >> 6;
    int n8  = rest % N8;  rest /= N8;
    int k16 = rest % K16; rest /= K16;
    int e   = rest;
    int gg = lane >> 2, tIG = lane & 3;
    int n = n8 * 8 + gg;
    int k = k16 * 16 + bidx * 8 + tIG * 2;
    float w0, w1;
    if (mode == 0)      { const float* B = W0 + e * 32768; w0 = B[k * 256 + n]; w1 = B[(k + 1) * 256 + n]; }
    else if (mode == 1) { const float* B = W1 + e * 65536; w0 = B[k * 256 + n]; w1 = B[(k + 1) * 256 + n]; }
    else if (mode == 2) { const float* B = W1 + e * 65536; w0 = B[n * 256 + k]; w1 = B[n * 256 + k + 1]; }
    else                { const float* B = W0 + e * 32768; w0 = B[n * 256 + k]; w1 = B[n * 256 + k + 1]; }
    __half v0 = __float2half_rn(w0), v1 = __float2half_rn(w1);
    dst[idx] = ((uint32_t)__half_as_ushort(v1) << 16) | (uint32_t)__half_as_ushort(v0);
}

__global__ void pre_kernel(float* __restrict__ out, int out_n, int zb,
                           const int* __restrict__ z,
                           const float* __restrict__ W0, const float* __restrict__ W1) {
    int bid = blockIdx.x, tid = threadIdx.x;
    if (bid < zb) {
        int i = bid * 256 + tid;
        if (i < out_n) out[i] = 0.0f;
    } else if (bid < zb + PREP_BLOCKS) {
        prep_one((bid - zb) * 256 + tid, W0, W1);
    } else {
        __shared__ int c[N_ELEM];
        if (tid < N_ELEM) c[tid] = 0;
        __syncthreads();
        for (int i = tid; i < N_ATOMS; i += 256)
            atomicAdd(&c[elem_of(__ldg(&z[i]))], 1);
        __syncthreads();
        if (tid == 0) {
            int off = 0;
            for (int e = 0; e < N_ELEM; e++) {
                d_offsets[e] = off; d_counts[e] = c[e]; d_cursor[e] = off;
                off += c[e];
            }
        }
    }
}

__global__ void scatter_kernel(const int* __restrict__ z, int n) {
    int a = blockIdx.x * blockDim.x + threadIdx.x;
    bool valid = a < n;
    int myE = valid ? elem_of(z[a]) : -1;
    int lane = threadIdx.x & 31;
    #pragma unroll
    for (int e = 0; e < N_ELEM; e++) {
        unsigned m = __ballot_sync(0xffffffffu, myE == e);
        if (!m) continue;
        int leader = __ffs(m) - 1;
        int base = 0;
        if (lane == leader) base = atomicAdd(&d_cursor[e], __popc(m));
        base = __shfl_sync(0xffffffffu, base, leader);
        if (myE == e) {
            int rank = __popc(m & ((1u << lane) - 1u));
            d_perm[base + rank] = a;
        }
    }
}

// ---------------- GEMM phase (fp16, software-pipelined B) ----------------
// USE_LO=true : two-term A (hi+lo) — L0 precision path.
// USE_LO=false: hi-only A — L1 forward + backward (half the MMAs and A-LDS).
// B frags for k16+1 prefetched into registers before k16's MMAs (no barriers).
// hi-block then lo-block issue: same-acc reuse distance 2*NF covers HMMA latency.
template <bool USE_LO, int K16, int NF, int N8TOT>
__device__ __forceinline__ void gemm_phase(
    const uint32_t* __restrict__ As, int psA,     // smem, A packed (hi at 0, lo at psA)
    const uint32_t* __restrict__ Bg,              // global, B packed (single fp16)
    int r16base, int n8base, int lane, float (&acc)[2][4][4])
{
    const uint32_t* Bp = Bg + ((n8base * 32 + lane) << 1);
    uint2 bcur[NF], bnxt[NF];
    #pragma unroll
    for (int nf = 0; nf < NF; nf++)
        bcur[nf] = *(const uint2*)&Bp[nf * 64];
    #pragma unroll 2
    for (int k16 = 0; k16 < K16; k16++) {
        uint4 ahi[2], alo[2];
        #pragma unroll
        for (int mf = 0; mf < 2; mf++) {
            int b = ((k16 * 4 + r16base + mf) * 32 + lane) * 4;
            ahi[mf] = *(const uint4*)&As[b];
            if (USE_LO) alo[mf] = *(const uint4*)&As[psA + b];
        }
        if (k16 + 1 < K16) {
            #pragma unroll
            for (int nf = 0; nf < NF; nf++)
                bnxt[nf] = *(const uint2*)&Bp[((k16 + 1) * N8TOT + nf) * 64];
        }
        #pragma unroll
        for (int nf = 0; nf < NF; nf++) {
            MMA_F16(acc[0][nf], ahi[0], bcur[nf]);
            MMA_F16(acc[1][nf], ahi[1], bcur[nf]);
        }
        if (USE_LO) {
            #pragma unroll
            for (int nf = 0; nf < NF; nf++) {
                MMA_F16(acc[0][nf], alo[0], bcur[nf]);
                MMA_F16(acc[1][nf], alo[1], bcur[nf]);
            }
        }
        #pragma unroll
        for (int nf = 0; nf < NF; nf++)
            bcur[nf] = bnxt[nf];
    }
}

// ---------------- fused MLP fwd + bwd, tensor-core ----------------
// block: 64 atoms, 512 threads = 16 warps in 2(M) x 8(N) grid; warp tile 32x32 (32x16 for B0).
__global__ void __launch_bounds__(MLP_THREADS)
mlp_mma_kernel(const float* __restrict__ fp, const int* __restrict__ image_idx,
               const float* __restrict__ b0g, const float* __restrict__ b1g,
               const float* __restrict__ W2g, const float* __restrict__ b2g,
               float* __restrict__ out_energy)
{
    const int e = blockIdx.y;
    const int cnt = d_counts[e];
    const int start = blockIdx.x * M_BLK;
    if (start >= cnt) return;
    const int off = d_offsets[e];
    const int na = min(M_BLK, cnt - start);

    extern __shared__ uint32_t smu[];
    uint32_t* buf0 = smu;              // 16384 u32 : h0 packed (hi/lo) -> dh0 packed (hi only)
    uint32_t* buf1 = smu + 16384;      // 16384 u32 : fpA packed -> dh1 packed (hi only)
    float*    o_s  = (float*)(smu + 32768);   // [64]
    int*      aidx = (int*)(o_s + M_BLK);     // [64]

    const int tid = threadIdx.x;
    const int warp = tid >> 5, lane = tid & 31;
    const int gg = lane >> 2, tIG = lane & 3;
    const int warpM = warp >> 3, warpN = warp & 7;   // 2 x 8
    const int r16base = warpM * 2;

    if (tid < M_BLK) {
        aidx[tid] = d_perm[off + start + min(tid, na - 1)];
        o_s[tid] = 0.0f;
    }
    __syncthreads();

    // ---- stage fingerprint tile as packed fp16 hi/lo A fragments (K=128, psA=4096) ----
    for (int p = tid; p < M_BLK * 64; p += MLP_THREADS) {
        int r = p >> 6, kp = p & 63;
        float2 v = *(const float2*)&fp[(size_t)aidx[r] * IN_DIM + 2 * kp];
        uint32_t hi, lo; split2(v.x, v.y, hi, lo);
        int idx = apk_idx(r, 2 * kp);
        buf1[idx] = hi; buf1[4096 + idx] = lo;
    }
    __syncthreads();

    const int r0 = warpM * 32 + gg;
    float acc[2][4][4];

    // ================= L0: preact0 = fpA @ W0 + b0 (two-term A) =================
    #pragma unroll
    for (int nf = 0; nf < 4; nf++) {
        int n0 = warpN * 32 + nf * 8 + 2 * tIG;
        float2 bb = *(const float2*)&b0g[e * HID + n0];
        acc[0][nf][0] = bb.x; acc[0][nf][1] = bb.y; acc[0][nf][2] = bb.x; acc[0][nf][3] = bb.y;
        acc[1][nf][0] = bb.x; acc[1][nf][1] = bb.y; acc[1][nf][2] = bb.x; acc[1][nf][3] = bb.y;
    }
    gemm_phase<true, 8, 4, 32>(buf1, 4096, d_B0pk + e * 16384, r16base, warpN * 4, lane, acc);
    // epilogue: h0 = tanh -> packed into buf0 (K=256 layout, psA=8192; lo kept for dtanh)
    #pragma unroll
    for (int mf = 0; mf < 2; mf++) {
        int ra = r0 + mf * 16, rb = ra + 8;
        #pragma unroll
        for (int nf = 0; nf < 4; nf++) {
            int n0 = warpN * 32 + nf * 8 + 2 * tIG;
            float t0 = tanhf(acc[mf][nf][0]), t1 = tanhf(acc[mf][nf][1]);
            float t2 = tanhf(acc[mf][nf][2]), t3 = tanhf(acc[mf][nf][3]);
            uint32_t hi, lo;
            split2(t0, t1, hi, lo);
            int i0 = apk_idx(ra, n0); buf0[i0] = hi; buf0[8192 + i0] = lo;
            split2(t2, t3, hi, lo);
            int i1 = apk_idx(rb, n0); buf0[i1] = hi; buf0[8192 + i1] = lo;
        }
    }
    __syncthreads();

    // ================= L1: preact1 = h0 @ W1 + b1 (hi-only A) =================
    #pragma unroll
    for (int nf = 0; nf < 4; nf++) {
        int n0 = warpN * 32 + nf * 8 + 2 * tIG;
        float2 bb = *(const float2*)&b1g[e * HID + n0];
        acc[0][nf][0] = bb.x; acc[0][nf][1] = bb.y; acc[0][nf][2] = bb.x; acc[0][nf][3] = bb.y;
        acc[1][nf][0] = bb.x; acc[1][nf][1] = bb.y; acc[1][nf][2] = bb.x; acc[1][nf][3] = bb.y;
    }
    gemm_phase<false, 16, 4, 32>(buf0, 8192, d_B1pk + e * 32768, r16base, warpN * 4, lane, acc);
    // epilogue: h1 = tanh; o += h1.W2; dh1 = W2*(1-h1^2) -> buf1 hi-only
    #pragma unroll
    for (int mf = 0; mf < 2; mf++) {
        int ra = r0 + mf * 16, rb = ra + 8;
        float orow0 = 0.0f, orow1 = 0.0f;
        #pragma unroll
        for (int nf = 0; nf < 4; nf++) {
            int n0 = warpN * 32 + nf * 8 + 2 * tIG;
            float2 w2v = *(const float2*)&W2g[e * HID + n0];
            float t0 = tanhf(acc[mf][nf][0]), t1 = tanhf(acc[mf][nf][1]);
            float t2 = tanhf(acc[mf][nf][2]), t3 = tanhf(acc[mf][nf][3]);
            orow0 += t0 * w2v.x + t1 * w2v.y;
            orow1 += t2 * w2v.x + t3 * w2v.y;
            float d0 = w2v.x * (1.0f - t0 * t0), d1 = w2v.y * (1.0f - t1 * t1);
            float d2 = w2v.x * (1.0f - t2 * t2), d3 = w2v.y * (1.0f - t3 * t3);
            buf1[apk_idx(ra, n0)] = pack_hi2(d0, d1);
            buf1[apk_idx(rb, n0)] = pack_hi2(d2, d3);
        }
        atomicAdd(&o_s[ra], orow0);
        atomicAdd(&o_s[rb], orow1);
    }
    __syncthreads();

    // energy: atomic segment-sum over images
    if (tid < na)
        atomicAdd(&out_energy[image_idx[aidx[tid]]], o_s[tid] + b2g[e]);

    // ================= B1: t = dh1 @ W1^T; dh0 = (1-h0^2)*t (hi-only A) =================
    #pragma unroll
    for (int mf = 0; mf < 2; mf++)
        #pragma unroll
        for (int nf = 0; nf < 4; nf++)
            #pragma unroll
            for (int q = 0; q < 4; q++) acc[mf][nf][q] = 0.0f;
    gemm_phase<false, 16, 4, 32>(buf1, 8192, d_BT1pk + e * 32768, r16base, warpN * 4, lane, acc);
    #pragma unroll
    for (int mf = 0; mf < 2; mf++) {
        int ra = r0 + mf * 16, rb = ra + 8;
        #pragma unroll
        for (int nf = 0; nf < 4; nf++) {
            int n0 = warpN * 32 + nf * 8 + 2 * tIG;
            int i0 = apk_idx(ra, n0), i1 = apk_idx(rb, n0);
            float2 h0a = unsplit2(buf0[i0], buf0[8192 + i0]);
            float2 h0b = unsplit2(buf0[i1], buf0[8192 + i1]);
            float v0 = (1.0f - h0a.x * h0a.x) * acc[mf][nf][0];
            float v1 = (1.0f - h0a.y * h0a.y) * acc[mf][nf][1];
            float v2 = (1.0f - h0b.x * h0b.x) * acc[mf][nf][2];
            float v3 = (1.0f - h0b.y * h0b.y) * acc[mf][nf][3];
            buf0[i0] = pack_hi2(v0, v1);
            buf0[i1] = pack_hi2(v2, v3);
        }
    }
    __syncthreads();

    // ================= B0: g = dh0 @ W0^T -> d_g (hi-only A) =================
    #pragma unroll
    for (int mf = 0; mf < 2; mf++)
        #pragma unroll
        for (int nf = 0; nf < 4; nf++)
            #pragma unroll
            for (int q = 0; q < 4; q++) acc[mf][nf][q] = 0.0f;
    gemm_phase<false, 16, 2, 16>(buf0, 8192, d_BT0pk + e * 16384, r16base, warpN * 2, lane, acc);
    #pragma unroll
    for (int mf = 0; mf < 2; mf++) {
        int ra = r0 + mf * 16, rb = ra + 8;
        #pragma unroll
        for (int nf = 0; nf < 2; nf++) {
            int n0 = warpN * 16 + nf * 8 + 2 * tIG;
            if (ra < na)
                *(float2*)&d_g[(size_t)aidx[ra] * IN_DIM + n0] =
                    make_float2(acc[mf][nf][0], acc[mf][nf][1]);
            if (rb < na)
                *(float2*)&d_g[(size_t)aidx[rb] * IN_DIM + n0] =
                    make_float2(acc[mf][nf][2], acc[mf][nf][3]);
        }
    }
}

// ---------------- sparse force scatter: forces = -fprimes^T @ g ----------------
__global__ void force_kernel(const int* __restrict__ rows,
                             const int* __restrict__ cols,
                             const float* __restrict__ vals,
                             int nnz, float* __restrict__ forces) {
    const int4*   r4 = (const int4*)rows;
    const int4*   c4 = (const int4*)cols;
    const float4* v4 = (const float4*)vals;
    const int nnz4 = nnz >> 2;
    int i = blockIdx.x * blockDim.x + threadIdx.x;
    int stride = gridDim.x * blockDim.x;
    for (; i < nnz4; i += stride) {
        int4 r = __ldg(&r4[i]);
        int4 c = __ldg(&c4[i]);
        float4 v = __ldg(&v4[i]);
        atomicAdd(&forces[c.x], -v.x * d_g[r.x]);
        atomicAdd(&forces[c.y], -v.y * d_g[r.y]);
        atomicAdd(&forces[c.z], -v.z * d_g[r.z]);
        atomicAdd(&forces[c.w], -v.w * d_g[r.w]);
    }
    int tail = nnz & 3;
    if (tail && blockIdx.x == 0 && threadIdx.x < tail) {
        int k = (nnz & ~3) + threadIdx.x;
        atomicAdd(&forces[cols[k]], -vals[k] * d_g[rows[k]]);
    }
}

// ---------------- launch ----------------
extern "C" void kernel_launch(void* const* d_in, const int* in_sizes, int n_in,
                              void* d_out, int out_size) {
    const float* fingerprints = (const float*)d_in[0];
    const int*   atomic_num   = (const int*)  d_in[1];
    const int*   image_idx    = (const int*)  d_in[2];
    const int*   fprime_rows  = (const int*)  d_in[3];
    const int*   fprime_cols  = (const int*)  d_in[4];
    const float* fprime_vals  = (const float*)d_in[5];
    const float* W0 = (const float*)d_in[6];
    const float* b0 = (const float*)d_in[7];
    const float* W1 = (const float*)d_in[8];
    const float* b1 = (const float*)d_in[9];
    const float* W2 = (const float*)d_in[10];
    const float* b2 = (const float*)d_in[11];
    float* out = (float*)d_out;                 // [0,500): energy, [500,150500): forces
    const int nnz = in_sizes[3];

    // fused prologue: zero out | fragment-pack weights (fp16) | element histogram
    const int zb = (out_size + 255) / 256;
    pre_kernel<<<zb + PREP_BLOCKS + 1, 256>>>(out, out_size, zb, atomic_num, W0, W1);

    // element bucketing
    scatter_kernel<<<(N_ATOMS + 255) / 256, 256>>>(atomic_num, N_ATOMS);

    // fused tensor-core MLP fwd+bwd
    const int smem_bytes = (32768 + M_BLK + M_BLK) * 4;   // 131,584 B
    cudaFuncSetAttribute(mlp_mma_kernel, cudaFuncAttributeMaxDynamicSharedMemorySize, 136 * 1024);
    dim3 grid((N_ATOMS + M_BLK - 1) / M_BLK, N_ELEM);
    mlp_mma_kernel<<<grid, MLP_THREADS, smem_bytes>>>(
        fingerprints, image_idx, b0, b1, W2, b2, out);

    // sparse force accumulation (vectorized x4)
    force_kernel<<<2048, 256>>>(fprime_rows, fprime_cols, fprime_vals, nnz, out + N_IMG);
}